// round 4
// baseline (speedup 1.0000x reference)
#include <cuda_runtime.h>
#include <math.h>

// Problem constants
#define CDIM 1024
#define NPIX 4096      // 64*64
#define TN_  3         // S_REF + 1
#define KSVD 500
#define SREF 2

// ---------------- scratch: one arena (no allocation) ----------------
// layout: [0, 3*1024*4096)            Xn  -> later holds fd (in-place debias+renorm)
//         [XN_ELEMS, +3*500*4096)     coef
#define XN_ELEMS   ((size_t)TN_ * CDIM * NPIX)
#define COEF_ELEMS ((size_t)TN_ * KSVD * NPIX)
__device__ float g_arena[XN_ELEMS + COEF_ELEMS];
__device__ float g_protos[SREF * CDIM];
__device__ float g_counts[SREF];
__device__ float g_proto[CDIM];
__device__ int   g_mask[SREF * NPIX];
__device__ unsigned long long g_part[SREF * NPIX];

// ---------------- column L2 normalize over channel dim ----------------
// layout: in[t][c][n], norm over c for each (t,n). in may equal out.
__global__ void norm_cols_kernel(const float* __restrict__ in, float* __restrict__ out) {
    int t = blockIdx.y;
    int n = blockIdx.x * blockDim.x + threadIdx.x;
    const float* p = in + (size_t)t * CDIM * NPIX + n;
    float ss = 0.f;
#pragma unroll 8
    for (int c = 0; c < CDIM; c++) {
        float v = p[(size_t)c * NPIX];
        ss += v * v;
    }
    float sc = 1.0f / fmaxf(sqrtf(ss), 1e-12f);
    float* q = out + (size_t)t * CDIM * NPIX + n;
#pragma unroll 8
    for (int c = 0; c < CDIM; c++) {
        q[(size_t)c * NPIX] = p[(size_t)c * NPIX] * sc;
    }
}

// ---------------- mask prep: dtype-sniff, counts, partmax init ----------------
__global__ void mask_prep_kernel(const void* __restrict__ mraw) {
    __shared__ int flag;
    __shared__ float sh0[256], sh1[256];
    int tid = threadIdx.x;
    if (tid == 0) flag = 0;
    __syncthreads();
    const unsigned char* b = (const unsigned char*)mraw;
    // If the buffer is int32 0/1, every byte at offset %4 != 0 is zero.
    int local = 0;
    for (int i = tid; i < SREF * NPIX; i += blockDim.x) {
        if ((i & 3) != 0 && b[i] != 0) local = 1;
    }
    if (local) atomicOr(&flag, 1);
    __syncthreads();
    int isbyte = flag;
    float c0 = 0.f, c1 = 0.f;
    for (int i = tid; i < SREF * NPIX; i += blockDim.x) {
        int v = isbyte ? (int)b[i] : ((const int*)mraw)[i];
        int m = (v != 0) ? 1 : 0;
        g_mask[i] = m;
        if (i < NPIX) c0 += (float)m; else c1 += (float)m;
        g_part[i] = 0ull;
    }
    sh0[tid] = c0; sh1[tid] = c1;
    __syncthreads();
    for (int s = 128; s > 0; s >>= 1) {
        if (tid < s) { sh0[tid] += sh0[tid + s]; sh1[tid] += sh1[tid + s]; }
        __syncthreads();
    }
    if (tid == 0) { g_counts[0] = sh0[0]; g_counts[1] = sh1[0]; }
}

// ---------------- generic fp32 SGEMM: Out = (SUB_C ? Csub - A*B : A*B) ----------------
// A element (k,m): TRANS_A ? A[k*lda+m] : A[m*lda+k].  B is B[k*N+n], ldb=N.
// BM=BN=128, BK=8, 256 threads, 8x8 per-thread tile.
// NOTE: Out == Csub aliasing is safe: each block reads its Csub tile only in
// its own epilogue, immediately before writing the same addresses.
template <bool TRANS_A, bool SUB_C>
__global__ void sgemm_kernel(const float* __restrict__ A, const float* __restrict__ B,
                             const float* __restrict__ Csub, float* __restrict__ Out,
                             int M, int N, int K, int lda,
                             size_t sA, size_t sB, size_t sC, size_t sO) {
    A += (size_t)blockIdx.z * sA;
    B += (size_t)blockIdx.z * sB;
    Out += (size_t)blockIdx.z * sO;
    if (SUB_C) Csub += (size_t)blockIdx.z * sC;

    const int m0 = blockIdx.y * 128;
    const int n0 = blockIdx.x * 128;

    __shared__ float As[8][128];
    __shared__ float Bs[8][128];

    int tid = threadIdx.x;
    int tx = tid & 15;   // column group
    int ty = tid >> 4;   // row group

    float acc[8][8];
#pragma unroll
    for (int i = 0; i < 8; i++)
#pragma unroll
        for (int j = 0; j < 8; j++) acc[i][j] = 0.f;

    for (int k0 = 0; k0 < K; k0 += 8) {
        // load A tile -> As[kk][mm]
#pragma unroll
        for (int l = 0; l < 4; l++) {
            int e = tid + l * 256;
            if (TRANS_A) {
                int mm = e & 127, kk = e >> 7;
                int gm = m0 + mm, gk = k0 + kk;
                float v = 0.f;
                if (gk < K && gm < M) v = A[(size_t)gk * lda + gm];
                As[kk][mm] = v;
            } else {
                int kk = e & 7, mm = e >> 3;
                int gm = m0 + mm, gk = k0 + kk;
                float v = 0.f;
                if (gk < K && gm < M) v = A[(size_t)gm * lda + gk];
                As[kk][mm] = v;
            }
        }
        // load B tile -> Bs[kk][nn]  (N is always a multiple of 128 here)
#pragma unroll
        for (int l = 0; l < 4; l++) {
            int e = tid + l * 256;
            int nn = e & 127, kk = e >> 7;
            int gk = k0 + kk;
            Bs[kk][nn] = (gk < K) ? B[(size_t)gk * N + (n0 + nn)] : 0.f;
        }
        __syncthreads();

#pragma unroll
        for (int kk = 0; kk < 8; kk++) {
            float4 a0 = *(const float4*)&As[kk][ty * 8];
            float4 a1 = *(const float4*)&As[kk][ty * 8 + 4];
            float4 b0 = *(const float4*)&Bs[kk][tx * 8];
            float4 b1 = *(const float4*)&Bs[kk][tx * 8 + 4];
            float a[8] = {a0.x, a0.y, a0.z, a0.w, a1.x, a1.y, a1.z, a1.w};
            float b[8] = {b0.x, b0.y, b0.z, b0.w, b1.x, b1.y, b1.z, b1.w};
#pragma unroll
            for (int i = 0; i < 8; i++)
#pragma unroll
                for (int j = 0; j < 8; j++) acc[i][j] += a[i] * b[j];
        }
        __syncthreads();
    }

#pragma unroll
    for (int i = 0; i < 8; i++) {
        int gm = m0 + ty * 8 + i;
        if (gm < M) {
#pragma unroll
            for (int j = 0; j < 8; j++) {
                int gn = n0 + tx * 8 + j;
                float r = acc[i][j];
                if (SUB_C) r = Csub[(size_t)gm * N + gn] - r;
                Out[(size_t)gm * N + gn] = r;
            }
        }
    }
}

// ---------------- masked prototypes: protos[s][c] = sum_n fd[s][c][n]*mask ----------------
__global__ void protos_kernel() {
    int c = blockIdx.x;
    int s = blockIdx.y;
    int tid = threadIdx.x;
    const float* row = g_arena + (size_t)s * CDIM * NPIX + (size_t)c * NPIX;  // fd
    const int* m = g_mask + s * NPIX;
    float sum = 0.f;
    for (int n = tid; n < NPIX; n += 256) sum += m[n] ? row[n] : 0.f;
    __shared__ float sh[256];
    sh[tid] = sum;
    __syncthreads();
    for (int st = 128; st > 0; st >>= 1) {
        if (tid < st) sh[tid] += sh[tid + st];
        __syncthreads();
    }
    if (tid == 0) g_protos[s * CDIM + c] = sh[0];
}

// ---------------- ref_prototype = l2norm(mean_s(protos/count)) ----------------
// 256 threads, each owns 4 channels.
__global__ void proto_kernel() {
    __shared__ float sh[256];
    int tid = threadIdx.x;
    float c0 = fmaxf(g_counts[0], 1.f);
    float c1 = fmaxf(g_counts[1], 1.f);
    float p[4];
    float ss = 0.f;
#pragma unroll
    for (int i = 0; i < 4; i++) {
        int c = tid * 4 + i;
        p[i] = 0.5f * (g_protos[c] / c0 + g_protos[CDIM + c] / c1);
        ss += p[i] * p[i];
    }
    sh[tid] = ss;
    __syncthreads();
    for (int st = 128; st > 0; st >>= 1) {
        if (tid < st) sh[tid] += sh[tid + st];
        __syncthreads();
    }
    float sc = 1.0f / fmaxf(sqrtf(sh[0]), 1e-12f);
#pragma unroll
    for (int i = 0; i < 4; i++) g_proto[tid * 4 + i] = p[i] * sc;
}

// ---------------- sim_fwd[xy] = sum_c fd_tgt[c][xy] * proto[c] ----------------
__global__ void simfwd_kernel(float* __restrict__ out) {
    int xy = blockIdx.x * blockDim.x + threadIdx.x;
    const float* tgt = g_arena + (size_t)2 * CDIM * NPIX;  // fd[2]
    float acc = 0.f;
#pragma unroll 8
    for (int c = 0; c < CDIM; c++) acc += tgt[(size_t)c * NPIX + xy] * g_proto[c];
    out[xy] = acc;
}

// ---------------- argmax over hw for each (s, xy): partial pass ----------------
__global__ void argmax_part_kernel(const float* __restrict__ sim) {
    int s = blockIdx.z;
    int xy = blockIdx.x * 256 + threadIdx.x;
    int hw0 = blockIdx.y * 256;
    const float* base = sim + (size_t)s * NPIX * NPIX + xy;
    float best = -1e30f;
    int bi = hw0;
#pragma unroll 4
    for (int i = 0; i < 256; i++) {
        float v = base[(size_t)(hw0 + i) * NPIX];
        if (v > best) { best = v; bi = hw0 + i; }   // strict > keeps first max
    }
    unsigned int key = __float_as_uint(best);
    key = (key & 0x80000000u) ? ~key : (key | 0x80000000u);  // order-preserving
    // low word = ~hw so ties pick the SMALLEST hw (jnp.argmax semantics)
    unsigned long long pk = ((unsigned long long)key << 32) | (unsigned int)(0xFFFFFFFFu - (unsigned)bi);
    atomicMax(&g_part[s * NPIX + xy], pk);
}

__global__ void votes_kernel(float* __restrict__ out) {
    int xy = blockIdx.x * blockDim.x + threadIdx.x;
    int v = 0;
#pragma unroll
    for (int s = 0; s < SREF; s++) {
        unsigned long long pk = g_part[s * NPIX + xy];
        int hw = (int)(0xFFFFFFFFu - (unsigned int)(pk & 0xFFFFFFFFu));
        v += g_mask[s * NPIX + hw];
    }
    out[xy] = (float)v;
}

// ---------------- launch ----------------
extern "C" void kernel_launch(void* const* d_in, const int* in_sizes, int n_in,
                              void* d_out, int out_size) {
    const float* fmaps = (const float*)d_in[0];
    const void*  masks = d_in[1];
    const float* basis = (const float*)d_in[2];
    float* out = (float*)d_out;

    float* sim    = out;                                   // 2*4096*4096
    float* simfwd = out + (size_t)SREF * NPIX * NPIX;      // 4096
    float* votes  = simfwd + NPIX;                         // 4096

    float* arena = nullptr;
    cudaGetSymbolAddress((void**)&arena, g_arena);
    float* Xn   = arena;             // becomes fd in place after steps 3+4
    float* coef = arena + XN_ELEMS;

    // 1. normalize fmaps over channels -> Xn
    norm_cols_kernel<<<dim3(NPIX / 256, TN_), 256>>>(fmaps, Xn);

    // 2. coef[t] = basis^T * Xn[t]   (M=500, N=4096, K=1024), A = basis (TRANS_A, lda=500)
    sgemm_kernel<true, false><<<dim3(32, (KSVD + 127) / 128, TN_), 256>>>(
        basis, Xn, nullptr, coef,
        KSVD, NPIX, CDIM, KSVD,
        0, (size_t)CDIM * NPIX, 0, (size_t)KSVD * NPIX);

    // 3. Xn[t] <- Xn[t] - basis * coef[t]  IN PLACE  (M=1024, N=4096, K=500)
    sgemm_kernel<false, true><<<dim3(32, CDIM / 128, TN_), 256>>>(
        basis, coef, Xn, Xn,
        CDIM, NPIX, KSVD, KSVD,
        0, (size_t)KSVD * NPIX, (size_t)CDIM * NPIX, (size_t)CDIM * NPIX);

    // 4. normalize in place -> fd (lives in Xn)
    norm_cols_kernel<<<dim3(NPIX / 256, TN_), 256>>>(Xn, Xn);

    // 5. mask prep (dtype sniff + counts + partmax init)
    mask_prep_kernel<<<1, 256>>>(masks);

    // 6. prototypes
    protos_kernel<<<dim3(CDIM, SREF), 256>>>();
    proto_kernel<<<1, 256>>>();

    // 7. sim_fwd
    simfwd_kernel<<<NPIX / 256, 256>>>(simfwd);

    // 8. sim[s] = fd_ref[s]^T * fd_tgt  (M=4096, N=4096, K=1024), A = fd[s] (TRANS_A, lda=4096)
    sgemm_kernel<true, false><<<dim3(32, 32, SREF), 256>>>(
        Xn, Xn + (size_t)2 * CDIM * NPIX, nullptr, sim,
        NPIX, NPIX, CDIM, NPIX,
        (size_t)CDIM * NPIX, 0, 0, (size_t)NPIX * NPIX);

    // 9. argmax + votes
    argmax_part_kernel<<<dim3(16, 16, SREF), 256>>>(sim);
    votes_kernel<<<NPIX / 256, 256>>>(votes);
}

// round 5
// speedup vs baseline: 1.1861x; 1.1861x over previous
#include <cuda_runtime.h>
#include <math.h>
#include <stdint.h>

// Problem constants
#define CDIM 1024
#define NPIX 4096      // 64*64
#define TN_  3         // S_REF + 1
#define KSVD 500
#define SREF 2

// ---------------- scratch: one arena (no allocation) ----------------
#define XN_ELEMS   ((size_t)TN_ * CDIM * NPIX)
#define COEF_ELEMS ((size_t)TN_ * KSVD * NPIX)
__device__ float g_arena[XN_ELEMS + COEF_ELEMS];
__device__ float g_protos[SREF * CDIM];
__device__ float g_counts[SREF];
__device__ float g_proto[CDIM];
__device__ int   g_mask[SREF * NPIX];
__device__ unsigned long long g_part[SREF * NPIX];

// ---------------- column L2 normalize over channel dim ----------------
// block = (32 pixels, 8 channel-parts); grid = (NPIX/32, T)
__global__ void norm_cols_kernel(const float* __restrict__ in, float* __restrict__ out) {
    int t = blockIdx.y;
    int pix = blockIdx.x * 32 + threadIdx.x;
    int part = threadIdx.y;
    const float* p = in + (size_t)t * CDIM * NPIX + pix;
    float* q = out + (size_t)t * CDIM * NPIX + pix;
    int c0 = part * 128;
    float ss = 0.f;
#pragma unroll 8
    for (int c = c0; c < c0 + 128; c++) {
        float v = p[(size_t)c * NPIX];
        ss += v * v;
    }
    __shared__ float sh[8][32];
    sh[part][threadIdx.x] = ss;
    __syncthreads();
    float tot = 0.f;
#pragma unroll
    for (int r = 0; r < 8; r++) tot += sh[r][threadIdx.x];
    float sc = 1.0f / fmaxf(sqrtf(tot), 1e-12f);
#pragma unroll 8
    for (int c = c0; c < c0 + 128; c++) {
        q[(size_t)c * NPIX] = p[(size_t)c * NPIX] * sc;
    }
}

// ---------------- mask prep: dtype-sniff, counts, partmax init ----------------
__global__ void mask_prep_kernel(const void* __restrict__ mraw) {
    __shared__ int flag;
    __shared__ float sh0[256], sh1[256];
    int tid = threadIdx.x;
    if (tid == 0) flag = 0;
    __syncthreads();
    const unsigned char* b = (const unsigned char*)mraw;
    int local = 0;
    for (int i = tid; i < SREF * NPIX; i += blockDim.x) {
        if ((i & 3) != 0 && b[i] != 0) local = 1;
    }
    if (local) atomicOr(&flag, 1);
    __syncthreads();
    int isbyte = flag;
    float c0 = 0.f, c1 = 0.f;
    for (int i = tid; i < SREF * NPIX; i += blockDim.x) {
        int v = isbyte ? (int)b[i] : ((const int*)mraw)[i];
        int m = (v != 0) ? 1 : 0;
        g_mask[i] = m;
        if (i < NPIX) c0 += (float)m; else c1 += (float)m;
        g_part[i] = 0ull;
    }
    sh0[tid] = c0; sh1[tid] = c1;
    __syncthreads();
    for (int s = 128; s > 0; s >>= 1) {
        if (tid < s) { sh0[tid] += sh0[tid + s]; sh1[tid] += sh1[tid + s]; }
        __syncthreads();
    }
    if (tid == 0) { g_counts[0] = sh0[0]; g_counts[1] = sh1[0]; }
}

// ---------------- TF32 helpers ----------------
__device__ __forceinline__ uint32_t f2tf32(float x) {
    uint32_t r;
    asm("cvt.rna.tf32.f32 %0, %1;" : "=r"(r) : "f"(x));
    return r;
}
__device__ __forceinline__ void mma_tf32(float* c, const uint32_t* a, const uint32_t* b) {
    asm volatile(
        "mma.sync.aligned.m16n8k8.row.col.f32.tf32.tf32.f32 "
        "{%0,%1,%2,%3},{%4,%5,%6,%7},{%8,%9},{%0,%1,%2,%3};\n"
        : "+f"(c[0]), "+f"(c[1]), "+f"(c[2]), "+f"(c[3])
        : "r"(a[0]), "r"(a[1]), "r"(a[2]), "r"(a[3]), "r"(b[0]), "r"(b[1]));
}

// ---------------- TF32 split GEMM: Out = (SUB_C ? Csub - A*B : A*B) ----------------
// A element (k,m): TRANS_A ? A[k*lda+m] : A[m*lda+k].  B[k*N+n].
// BM=BN=128, BK=16, 256 threads (8 warps, 2x4), warp tile 64x32.
// Precision: hi/lo tf32 split, computes hi*hi + hi*lo + lo*hi (fp32-like).
// Out==Csub aliasing safe: Csub read only in this block's epilogue.
template <bool TRANS_A, bool SUB_C>
__global__ void __launch_bounds__(256, 1)
tf32gemm_kernel(const float* __restrict__ A, const float* __restrict__ B,
                const float* __restrict__ Csub, float* __restrict__ Out,
                int M, int N, int K, int lda,
                size_t sA, size_t sB, size_t sC, size_t sO) {
    A += (size_t)blockIdx.z * sA;
    B += (size_t)blockIdx.z * sB;
    Out += (size_t)blockIdx.z * sO;
    if (SUB_C) Csub += (size_t)blockIdx.z * sC;

    const int m0 = blockIdx.y * 128;
    const int n0 = blockIdx.x * 128;

    __shared__ uint32_t As_hi[16][136], As_lo[16][136];
    __shared__ uint32_t Bs_hi[16][136], Bs_lo[16][136];

    const int tid = threadIdx.x;
    const int lane = tid & 31;
    const int w = tid >> 5;
    const int wm = w & 1;        // 0..1  (M direction, 64 rows each)
    const int wn = w >> 1;       // 0..3  (N direction, 32 cols each)
    const int g = lane >> 2;     // group id 0..7
    const int tg = lane & 3;     // thread in group

    float acc[4][4][4];
#pragma unroll
    for (int i = 0; i < 4; i++)
#pragma unroll
        for (int j = 0; j < 4; j++)
#pragma unroll
            for (int r = 0; r < 4; r++) acc[i][j][r] = 0.f;

    for (int k0 = 0; k0 < K; k0 += 16) {
        // ---- load + split A tile (128 x 16) ----
#pragma unroll
        for (int l = 0; l < 8; l++) {
            int e = tid + l * 256;
            int mm, kk;
            if (TRANS_A) { mm = e & 127; kk = e >> 7; }
            else         { kk = e & 15;  mm = e >> 4; }
            int gm = m0 + mm, gk = k0 + kk;
            float v = 0.f;
            if (gk < K && gm < M)
                v = TRANS_A ? A[(size_t)gk * lda + gm] : A[(size_t)gm * lda + gk];
            uint32_t hi = f2tf32(v);
            float lo = v - __uint_as_float(hi);
            As_hi[kk][mm] = hi;
            As_lo[kk][mm] = f2tf32(lo);
        }
        // ---- load + split B tile (16 x 128) ----
#pragma unroll
        for (int l = 0; l < 8; l++) {
            int e = tid + l * 256;
            int nn = e & 127, kk = e >> 7;
            int gk = k0 + kk;
            float v = (gk < K) ? B[(size_t)gk * N + (n0 + nn)] : 0.f;
            uint32_t hi = f2tf32(v);
            float lo = v - __uint_as_float(hi);
            Bs_hi[kk][nn] = hi;
            Bs_lo[kk][nn] = f2tf32(lo);
        }
        __syncthreads();

#pragma unroll
        for (int slice = 0; slice < 2; slice++) {
            const int ks = slice * 8;
            uint32_t ah[4][4], al[4][4], bh[4][2], bl[4][2];
#pragma unroll
            for (int i = 0; i < 4; i++) {
                int m = wm * 64 + i * 16 + g;
                ah[i][0] = As_hi[ks + tg][m];
                ah[i][1] = As_hi[ks + tg][m + 8];
                ah[i][2] = As_hi[ks + tg + 4][m];
                ah[i][3] = As_hi[ks + tg + 4][m + 8];
                al[i][0] = As_lo[ks + tg][m];
                al[i][1] = As_lo[ks + tg][m + 8];
                al[i][2] = As_lo[ks + tg + 4][m];
                al[i][3] = As_lo[ks + tg + 4][m + 8];
            }
#pragma unroll
            for (int j = 0; j < 4; j++) {
                int n = wn * 32 + j * 8 + g;
                bh[j][0] = Bs_hi[ks + tg][n];
                bh[j][1] = Bs_hi[ks + tg + 4][n];
                bl[j][0] = Bs_lo[ks + tg][n];
                bl[j][1] = Bs_lo[ks + tg + 4][n];
            }
#pragma unroll
            for (int i = 0; i < 4; i++)
#pragma unroll
                for (int j = 0; j < 4; j++) {
                    mma_tf32(acc[i][j], ah[i], bh[j]);
                    mma_tf32(acc[i][j], ah[i], bl[j]);
                    mma_tf32(acc[i][j], al[i], bh[j]);
                }
        }
        __syncthreads();
    }

    // ---- epilogue ----
#pragma unroll
    for (int i = 0; i < 4; i++) {
        int r0 = m0 + wm * 64 + i * 16 + g;
        int r1 = r0 + 8;
#pragma unroll
        for (int j = 0; j < 4; j++) {
            int cc = n0 + wn * 32 + j * 8 + 2 * tg;
            const float* a4 = acc[i][j];
            if (r0 < M) {
                float v0 = a4[0], v1 = a4[1];
                if (SUB_C) {
                    v0 = Csub[(size_t)r0 * N + cc] - v0;
                    v1 = Csub[(size_t)r0 * N + cc + 1] - v1;
                }
                Out[(size_t)r0 * N + cc] = v0;
                Out[(size_t)r0 * N + cc + 1] = v1;
            }
            if (r1 < M) {
                float v2 = a4[2], v3 = a4[3];
                if (SUB_C) {
                    v2 = Csub[(size_t)r1 * N + cc] - v2;
                    v3 = Csub[(size_t)r1 * N + cc + 1] - v3;
                }
                Out[(size_t)r1 * N + cc] = v2;
                Out[(size_t)r1 * N + cc + 1] = v3;
            }
        }
    }
}

// ---------------- masked prototypes ----------------
__global__ void protos_kernel() {
    int c = blockIdx.x;
    int s = blockIdx.y;
    int tid = threadIdx.x;
    const float* row = g_arena + (size_t)s * CDIM * NPIX + (size_t)c * NPIX;  // fd
    const int* m = g_mask + s * NPIX;
    float sum = 0.f;
    for (int n = tid; n < NPIX; n += 256) sum += m[n] ? row[n] : 0.f;
    __shared__ float sh[256];
    sh[tid] = sum;
    __syncthreads();
    for (int st = 128; st > 0; st >>= 1) {
        if (tid < st) sh[tid] += sh[tid + st];
        __syncthreads();
    }
    if (tid == 0) g_protos[s * CDIM + c] = sh[0];
}

// ---------------- ref_prototype = l2norm(mean_s(protos/count)) ----------------
__global__ void proto_kernel() {
    __shared__ float sh[256];
    int tid = threadIdx.x;
    float c0 = fmaxf(g_counts[0], 1.f);
    float c1 = fmaxf(g_counts[1], 1.f);
    float p[4];
    float ss = 0.f;
#pragma unroll
    for (int i = 0; i < 4; i++) {
        int c = tid * 4 + i;
        p[i] = 0.5f * (g_protos[c] / c0 + g_protos[CDIM + c] / c1);
        ss += p[i] * p[i];
    }
    sh[tid] = ss;
    __syncthreads();
    for (int st = 128; st > 0; st >>= 1) {
        if (tid < st) sh[tid] += sh[tid + st];
        __syncthreads();
    }
    float sc = 1.0f / fmaxf(sqrtf(sh[0]), 1e-12f);
#pragma unroll
    for (int i = 0; i < 4; i++) g_proto[tid * 4 + i] = p[i] * sc;
}

// ---------------- sim_fwd ----------------
__global__ void simfwd_kernel(float* __restrict__ out) {
    int xy = blockIdx.x * blockDim.x + threadIdx.x;
    const float* tgt = g_arena + (size_t)2 * CDIM * NPIX;  // fd[2]
    float acc = 0.f;
#pragma unroll 8
    for (int c = 0; c < CDIM; c++) acc += tgt[(size_t)c * NPIX + xy] * g_proto[c];
    out[xy] = acc;
}

// ---------------- argmax over hw for each (s, xy) ----------------
__global__ void argmax_part_kernel(const float* __restrict__ sim) {
    int s = blockIdx.z;
    int xy = blockIdx.x * 256 + threadIdx.x;
    int hw0 = blockIdx.y * 256;
    const float* base = sim + (size_t)s * NPIX * NPIX + xy;
    float best = -1e30f;
    int bi = hw0;
#pragma unroll 4
    for (int i = 0; i < 256; i++) {
        float v = base[(size_t)(hw0 + i) * NPIX];
        if (v > best) { best = v; bi = hw0 + i; }
    }
    unsigned int key = __float_as_uint(best);
    key = (key & 0x80000000u) ? ~key : (key | 0x80000000u);
    unsigned long long pk = ((unsigned long long)key << 32) | (unsigned int)(0xFFFFFFFFu - (unsigned)bi);
    atomicMax(&g_part[s * NPIX + xy], pk);
}

__global__ void votes_kernel(float* __restrict__ out) {
    int xy = blockIdx.x * blockDim.x + threadIdx.x;
    int v = 0;
#pragma unroll
    for (int s = 0; s < SREF; s++) {
        unsigned long long pk = g_part[s * NPIX + xy];
        int hw = (int)(0xFFFFFFFFu - (unsigned int)(pk & 0xFFFFFFFFu));
        v += g_mask[s * NPIX + hw];
    }
    out[xy] = (float)v;
}

// ---------------- launch ----------------
extern "C" void kernel_launch(void* const* d_in, const int* in_sizes, int n_in,
                              void* d_out, int out_size) {
    const float* fmaps = (const float*)d_in[0];
    const void*  masks = d_in[1];
    const float* basis = (const float*)d_in[2];
    float* out = (float*)d_out;

    float* sim    = out;
    float* simfwd = out + (size_t)SREF * NPIX * NPIX;
    float* votes  = simfwd + NPIX;

    float* arena = nullptr;
    cudaGetSymbolAddress((void**)&arena, g_arena);
    float* Xn   = arena;             // becomes fd in place after steps 3+4
    float* coef = arena + XN_ELEMS;

    dim3 nblk(32, 8);

    // 1. normalize fmaps over channels -> Xn
    norm_cols_kernel<<<dim3(NPIX / 32, TN_), nblk>>>(fmaps, Xn);

    // 2. coef[t] = basis^T * Xn[t]  (M=500, N=4096, K=1024), A=basis TRANS, lda=500
    tf32gemm_kernel<true, false><<<dim3(32, 4, TN_), 256>>>(
        basis, Xn, nullptr, coef,
        KSVD, NPIX, CDIM, KSVD,
        0, (size_t)CDIM * NPIX, 0, (size_t)KSVD * NPIX);

    // 3. Xn[t] <- Xn[t] - basis * coef[t]  IN PLACE  (M=1024, N=4096, K=500)
    tf32gemm_kernel<false, true><<<dim3(32, 8, TN_), 256>>>(
        basis, coef, Xn, Xn,
        CDIM, NPIX, KSVD, KSVD,
        0, (size_t)KSVD * NPIX, (size_t)CDIM * NPIX, (size_t)CDIM * NPIX);

    // 4. normalize in place -> fd (lives in Xn)
    norm_cols_kernel<<<dim3(NPIX / 32, TN_), nblk>>>(Xn, Xn);

    // 5. mask prep
    mask_prep_kernel<<<1, 256>>>(masks);

    // 6. prototypes
    protos_kernel<<<dim3(CDIM, SREF), 256>>>();
    proto_kernel<<<1, 256>>>();

    // 7. sim_fwd
    simfwd_kernel<<<NPIX / 256, 256>>>(simfwd);

    // 8. sim[s] = fd_ref[s]^T * fd_tgt  (M=4096, N=4096, K=1024)
    tf32gemm_kernel<true, false><<<dim3(32, 32, SREF), 256>>>(
        Xn, Xn + (size_t)2 * CDIM * NPIX, nullptr, sim,
        NPIX, NPIX, CDIM, NPIX,
        (size_t)CDIM * NPIX, 0, 0, (size_t)NPIX * NPIX);

    // 9. argmax + votes
    argmax_part_kernel<<<dim3(16, 16, SREF), 256>>>(sim);
    votes_kernel<<<NPIX / 256, 256>>>(votes);
}

// round 7
// speedup vs baseline: 1.5211x; 1.2824x over previous
#include <cuda_runtime.h>
#include <math.h>
#include <stdint.h>

// Problem constants
#define CDIM 1024
#define NPIX 4096      // 64*64
#define TN_  3         // S_REF + 1
#define KSVD 500
#define KPAD 512
#define SREF 2

// GEMM tile config
#define BM 128
#define BN 128
#define BK 32
#define APITCH 36                       // words per smem row (144B: 16B-aligned, conflict-free)
#define TILE_WORDS (128 * APITCH)
#define STAGE_WORDS (4 * TILE_WORDS)    // Ahi | Alo | Bhi | Blo
#define SMEM_DYN (2 * STAGE_WORDS * 4)  // 147456 bytes

// ---------------- scratch (device globals; no allocation) ----------------
__device__ float g_xnt[(size_t)TN_ * NPIX * CDIM];   // fp32 [t][n][c]; Xn -> Xd -> fd in place
__device__ float g_hi [(size_t)TN_ * NPIX * CDIM];   // tf32 hi of Xn, later of fd
__device__ float g_lo [(size_t)TN_ * NPIX * CDIM];   // tf32 lo
__device__ float g_chi[(size_t)TN_ * NPIX * KPAD];   // coef hi [t][n][j]
__device__ float g_clo[(size_t)TN_ * NPIX * KPAD];
__device__ float g_bT_hi[KPAD * CDIM];               // basisT [j][c], rows >=500 zero
__device__ float g_bT_lo[KPAD * CDIM];
__device__ float g_bc_hi[CDIM * KPAD];               // basis  [c][j], cols >=500 zero
__device__ float g_bc_lo[CDIM * KPAD];
__device__ float g_nrm[TN_ * NPIX];
__device__ float g_protpart[SREF * 32 * CDIM];
__device__ float g_protos[SREF * CDIM];
__device__ float g_counts[SREF];
__device__ float g_proto[CDIM];
__device__ int   g_mask[SREF * NPIX];
__device__ unsigned long long g_part[SREF * NPIX];

// ---------------- helpers ----------------
__device__ __forceinline__ uint32_t smem_u32(const void* p) {
    uint32_t a;
    asm("{ .reg .u64 t; cvta.to.shared.u64 t, %1; cvt.u32.u64 %0, t; }" : "=r"(a) : "l"(p));
    return a;
}
__device__ __forceinline__ void cp16(uint32_t dst, const void* src) {
    asm volatile("cp.async.cg.shared.global [%0], [%1], 16;" :: "r"(dst), "l"(src) : "memory");
}
#define CP_COMMIT() asm volatile("cp.async.commit_group;" ::: "memory")
#define CP_WAIT1()  asm volatile("cp.async.wait_group 1;" ::: "memory")
#define CP_WAIT0()  asm volatile("cp.async.wait_group 0;" ::: "memory")

__device__ __forceinline__ uint32_t f2tf32(float x) {
    uint32_t r;
    asm("cvt.rna.tf32.f32 %0, %1;" : "=r"(r) : "f"(x));
    return r;
}
__device__ __forceinline__ void mma_tf32(float* c, const uint32_t* a, const uint32_t* b) {
    asm volatile(
        "mma.sync.aligned.m16n8k8.row.col.f32.tf32.tf32.f32 "
        "{%0,%1,%2,%3},{%4,%5,%6,%7},{%8,%9},{%0,%1,%2,%3};\n"
        : "+f"(c[0]), "+f"(c[1]), "+f"(c[2]), "+f"(c[3])
        : "r"(a[0]), "r"(a[1]), "r"(a[2]), "r"(a[3]), "r"(b[0]), "r"(b[1]));
}

// ================= pre-split tf32 GEMM: D[m][n] = sum_k A[m,k]*B[n,k] =================
// Operands pre-split into tf32 hi/lo fp32-word arrays, K multiple of 32, M,N mult of 128.
// MODE 0: O1 = D (fp32). MODE 1: O1/O2 = tf32 split of D. MODE 2: O1 = Csub - D (in-place ok).
template <int MODE>
__global__ void __launch_bounds__(256, 1)
tc_gemm(const float* __restrict__ Ahi, const float* __restrict__ Alo, int lda, size_t zsA,
        const float* __restrict__ Bhi, const float* __restrict__ Blo, int ldb, size_t zsB,
        float* __restrict__ O1, float* __restrict__ O2, int ldo, size_t zsO,
        const float* __restrict__ Csub, size_t zsC, int K) {
    extern __shared__ float sm[];
    const int tid = threadIdx.x;
    const int lane = tid & 31, w = tid >> 5;
    const int wm = w & 1, wn = w >> 1;        // 2 x 4 warps, warp tile 64x32
    const int g = lane >> 2, tg = lane & 3;

    Ahi += (size_t)blockIdx.z * zsA;  Alo += (size_t)blockIdx.z * zsA;
    Bhi += (size_t)blockIdx.z * zsB;  Blo += (size_t)blockIdx.z * zsB;
    O1  += (size_t)blockIdx.z * zsO;
    if (MODE == 1) O2 += (size_t)blockIdx.z * zsO;
    if (MODE == 2) Csub += (size_t)blockIdx.z * zsC;
    const int m0 = blockIdx.y * BM;
    const int n0 = blockIdx.x * BN;

    const uint32_t sbase = smem_u32(sm);

    float acc[4][4][4];
#pragma unroll
    for (int i = 0; i < 4; i++)
#pragma unroll
        for (int j = 0; j < 4; j++)
#pragma unroll
            for (int r = 0; r < 4; r++) acc[i][j][r] = 0.f;

    // ---- async loader: 1024 16B-chunks per array, 4 per thread ----
    auto issue = [&](int st, int k0) {
        uint32_t sb = sbase + (uint32_t)st * STAGE_WORDS * 4;
#pragma unroll
        for (int p = 0; p < 4; p++) {
            int ch = p * 256 + tid;
            int row = ch >> 3, q = ch & 7;
            uint32_t d = sb + (uint32_t)(row * APITCH + q * 4) * 4;
            const size_t ao = (size_t)(m0 + row) * lda + k0 + q * 4;
            const size_t bo = (size_t)(n0 + row) * ldb + k0 + q * 4;
            cp16(d,                       Ahi + ao);
            cp16(d + TILE_WORDS * 4,      Alo + ao);
            cp16(d + 2 * TILE_WORDS * 4,  Bhi + bo);
            cp16(d + 3 * TILE_WORDS * 4,  Blo + bo);
        }
    };

    issue(0, 0);
    CP_COMMIT();

    const int NT = K >> 5;
    for (int it = 0; it < NT; it++) {
        if (it + 1 < NT) {
            issue((it + 1) & 1, (it + 1) * BK);
            CP_COMMIT();
            CP_WAIT1();
        } else {
            CP_WAIT0();
        }
        __syncthreads();

        const float* sA_hi = sm + (size_t)(it & 1) * STAGE_WORDS;
        const float* sA_lo = sA_hi + TILE_WORDS;
        const float* sB_hi = sA_hi + 2 * TILE_WORDS;
        const float* sB_lo = sA_hi + 3 * TILE_WORDS;

#pragma unroll
        for (int ks = 0; ks < BK; ks += 8) {
            uint32_t ah[4][4], al[4][4], bh[4][2], bl[4][2];
#pragma unroll
            for (int i = 0; i < 4; i++) {
                int m = wm * 64 + i * 16 + g;
                ah[i][0] = __float_as_uint(sA_hi[m * APITCH + ks + tg]);
                ah[i][1] = __float_as_uint(sA_hi[(m + 8) * APITCH + ks + tg]);
                ah[i][2] = __float_as_uint(sA_hi[m * APITCH + ks + tg + 4]);
                ah[i][3] = __float_as_uint(sA_hi[(m + 8) * APITCH + ks + tg + 4]);
                al[i][0] = __float_as_uint(sA_lo[m * APITCH + ks + tg]);
                al[i][1] = __float_as_uint(sA_lo[(m + 8) * APITCH + ks + tg]);
                al[i][2] = __float_as_uint(sA_lo[m * APITCH + ks + tg + 4]);
                al[i][3] = __float_as_uint(sA_lo[(m + 8) * APITCH + ks + tg + 4]);
            }
#pragma unroll
            for (int j = 0; j < 4; j++) {
                int n = wn * 32 + j * 8 + g;
                bh[j][0] = __float_as_uint(sB_hi[n * APITCH + ks + tg]);
                bh[j][1] = __float_as_uint(sB_hi[n * APITCH + ks + tg + 4]);
                bl[j][0] = __float_as_uint(sB_lo[n * APITCH + ks + tg]);
                bl[j][1] = __float_as_uint(sB_lo[n * APITCH + ks + tg + 4]);
            }
#pragma unroll
            for (int i = 0; i < 4; i++)
#pragma unroll
                for (int j = 0; j < 4; j++) {
                    mma_tf32(acc[i][j], ah[i], bh[j]);
                    mma_tf32(acc[i][j], ah[i], bl[j]);
                    mma_tf32(acc[i][j], al[i], bh[j]);
                }
        }
        __syncthreads();
    }

    // ---- epilogue ----
#pragma unroll
    for (int i = 0; i < 4; i++) {
        int r0 = m0 + wm * 64 + i * 16 + g;
        int r1 = r0 + 8;
#pragma unroll
        for (int j = 0; j < 4; j++) {
            int cc = n0 + wn * 32 + j * 8 + 2 * tg;
            float v0 = acc[i][j][0], v1 = acc[i][j][1];
            float v2 = acc[i][j][2], v3 = acc[i][j][3];
            size_t o0 = (size_t)r0 * ldo + cc;
            size_t o1 = (size_t)r1 * ldo + cc;
            if (MODE == 0) {
                O1[o0] = v0; O1[o0 + 1] = v1;
                O1[o1] = v2; O1[o1 + 1] = v3;
            } else if (MODE == 1) {
                uint32_t h;
                h = f2tf32(v0); O1[o0]     = __uint_as_float(h); O2[o0]     = __uint_as_float(f2tf32(v0 - __uint_as_float(h)));
                h = f2tf32(v1); O1[o0 + 1] = __uint_as_float(h); O2[o0 + 1] = __uint_as_float(f2tf32(v1 - __uint_as_float(h)));
                h = f2tf32(v2); O1[o1]     = __uint_as_float(h); O2[o1]     = __uint_as_float(f2tf32(v2 - __uint_as_float(h)));
                h = f2tf32(v3); O1[o1 + 1] = __uint_as_float(h); O2[o1 + 1] = __uint_as_float(f2tf32(v3 - __uint_as_float(h)));
            } else {
                O1[o0]     = Csub[o0]     - v0;
                O1[o0 + 1] = Csub[o0 + 1] - v1;
                O1[o1]     = Csub[o1]     - v2;
                O1[o1 + 1] = Csub[o1 + 1] - v3;
            }
        }
    }
}

// ================= prep / aux kernels =================

// channel norms of fmaps[t][c][n]
__global__ void norms_kernel(const float* __restrict__ in) {
    int t = blockIdx.y;
    int pix = blockIdx.x * 32 + threadIdx.x;
    int part = threadIdx.y;
    const float* p = in + (size_t)t * CDIM * NPIX + pix;
    float ss = 0.f;
#pragma unroll 8
    for (int c = part * 128; c < part * 128 + 128; c++) {
        float v = p[(size_t)c * NPIX];
        ss += v * v;
    }
    __shared__ float sh[8][33];
    sh[part][threadIdx.x] = ss;
    __syncthreads();
    if (part == 0) {
        float tot = 0.f;
#pragma unroll
        for (int r = 0; r < 8; r++) tot += sh[r][threadIdx.x];
        g_nrm[t * NPIX + pix] = 1.0f / fmaxf(sqrtf(tot), 1e-12f);
    }
}

// XnT[t][n][c] (fp32 + tf32 hi/lo) = fmaps[t][c][n] * nrm[t][n]
__global__ void transpose_scale_split_kernel(const float* __restrict__ in) {
    __shared__ float sh[32][33];
    int t = blockIdx.z;
    int c0 = blockIdx.x * 32, n0 = blockIdx.y * 32;
    const float* p = in + (size_t)t * CDIM * NPIX;
    for (int i = threadIdx.y; i < 32; i += 8)
        sh[i][threadIdx.x] = p[(size_t)(c0 + i) * NPIX + n0 + threadIdx.x];
    __syncthreads();
    size_t base = (size_t)t * NPIX * CDIM;
    for (int i = threadIdx.y; i < 32; i += 8) {
        int n = n0 + i;
        float v = sh[threadIdx.x][i] * g_nrm[t * NPIX + n];
        size_t o = base + (size_t)n * CDIM + c0 + threadIdx.x;
        g_xnt[o] = v;
        uint32_t h = f2tf32(v);
        g_hi[o] = __uint_as_float(h);
        g_lo[o] = __uint_as_float(f2tf32(v - __uint_as_float(h)));
    }
}

// basisT[j][c] split (rows j>=500 zero)
__global__ void basis_prepT_kernel(const float* __restrict__ basis) {
    __shared__ float sh[32][33];
    int c0 = blockIdx.x * 32, j0 = blockIdx.y * 32;
    for (int i = threadIdx.y; i < 32; i += 8) {
        int j = j0 + threadIdx.x;
        sh[i][threadIdx.x] = (j < KSVD) ? basis[(size_t)(c0 + i) * KSVD + j] : 0.f;
    }
    __syncthreads();
    for (int i = threadIdx.y; i < 32; i += 8) {
        float v = sh[threadIdx.x][i];
        size_t o = (size_t)(j0 + i) * CDIM + c0 + threadIdx.x;
        uint32_t h = f2tf32(v);
        g_bT_hi[o] = __uint_as_float(h);
        g_bT_lo[o] = __uint_as_float(f2tf32(v - __uint_as_float(h)));
    }
}

// basis[c][j] split (cols j>=500 zero)
__global__ void basis_prepC_kernel(const float* __restrict__ basis) {
    int idx = blockIdx.x * 256 + threadIdx.x;
    int c = idx >> 9, j = idx & (KPAD - 1);
    float v = (j < KSVD) ? basis[(size_t)c * KSVD + j] : 0.f;
    uint32_t h = f2tf32(v);
    g_bc_hi[idx] = __uint_as_float(h);
    g_bc_lo[idx] = __uint_as_float(f2tf32(v - __uint_as_float(h)));
}

// row L2 normalize in place + write tf32 hi/lo split
__global__ void norm_rows_split_kernel() {
    size_t row = blockIdx.x;
    float4* p = (float4*)(g_xnt + row * CDIM);
    int tid = threadIdx.x;
    float4 v = p[tid];
    float ss = v.x * v.x + v.y * v.y + v.z * v.z + v.w * v.w;
    __shared__ float sh[256];
    sh[tid] = ss;
    __syncthreads();
    for (int s = 128; s > 0; s >>= 1) {
        if (tid < s) sh[tid] += sh[tid + s];
        __syncthreads();
    }
    float sc = 1.0f / fmaxf(sqrtf(sh[0]), 1e-12f);
    v.x *= sc; v.y *= sc; v.z *= sc; v.w *= sc;
    p[tid] = v;
    size_t o = row * CDIM + tid * 4;
    float vv[4] = {v.x, v.y, v.z, v.w};
#pragma unroll
    for (int r = 0; r < 4; r++) {
        uint32_t h = f2tf32(vv[r]);
        g_hi[o + r] = __uint_as_float(h);
        g_lo[o + r] = __uint_as_float(f2tf32(vv[r] - __uint_as_float(h)));
    }
}

// mask prep: dtype-sniff, counts, partmax init
__global__ void mask_prep_kernel(const void* __restrict__ mraw) {
    __shared__ int flag;
    __shared__ float sh0[256], sh1[256];
    int tid = threadIdx.x;
    if (tid == 0) flag = 0;
    __syncthreads();
    const unsigned char* b = (const unsigned char*)mraw;
    int local = 0;
    for (int i = tid; i < SREF * NPIX; i += blockDim.x)
        if ((i & 3) != 0 && b[i] != 0) local = 1;
    if (local) atomicOr(&flag, 1);
    __syncthreads();
    int isbyte = flag;
    float c0 = 0.f, c1 = 0.f;
    for (int i = tid; i < SREF * NPIX; i += blockDim.x) {
        int v = isbyte ? (int)b[i] : ((const int*)mraw)[i];
        int m = (v != 0) ? 1 : 0;
        g_mask[i] = m;
        if (i < NPIX) c0 += (float)m; else c1 += (float)m;
        g_part[i] = 0ull;
    }
    sh0[tid] = c0; sh1[tid] = c1;
    __syncthreads();
    for (int s = 128; s > 0; s >>= 1) {
        if (tid < s) { sh0[tid] += sh0[tid + s]; sh1[tid] += sh1[tid + s]; }
        __syncthreads();
    }
    if (tid == 0) { g_counts[0] = sh0[0]; g_counts[1] = sh1[0]; }
}

// protos partials (deterministic)
__global__ void protos_part_kernel() {
    int s = blockIdx.z, nb = blockIdx.y;
    int c = blockIdx.x * 256 + threadIdx.x;
    const float* base = g_xnt + (size_t)s * NPIX * CDIM;
    float acc = 0.f;
    for (int n = nb * 128; n < nb * 128 + 128; n++)
        if (g_mask[s * NPIX + n]) acc += base[(size_t)n * CDIM + c];
    g_protpart[(s * 32 + nb) * CDIM + c] = acc;
}
__global__ void protos_reduce_kernel() {
    int s = blockIdx.y;
    int c = blockIdx.x * 256 + threadIdx.x;
    float a = 0.f;
#pragma unroll
    for (int nb = 0; nb < 32; nb++) a += g_protpart[(s * 32 + nb) * CDIM + c];
    g_protos[s * CDIM + c] = a;
}

__global__ void proto_kernel() {
    __shared__ float sh[256];
    int tid = threadIdx.x;
    float c0 = fmaxf(g_counts[0], 1.f);
    float c1 = fmaxf(g_counts[1], 1.f);
    float p[4];
    float ss = 0.f;
#pragma unroll
    for (int i = 0; i < 4; i++) {
        int c = tid * 4 + i;
        p[i] = 0.5f * (g_protos[c] / c0 + g_protos[CDIM + c] / c1);
        ss += p[i] * p[i];
    }
    sh[tid] = ss;
    __syncthreads();
    for (int st = 128; st > 0; st >>= 1) {
        if (tid < st) sh[tid] += sh[tid + st];
        __syncthreads();
    }
    float sc = 1.0f / fmaxf(sqrtf(sh[0]), 1e-12f);
#pragma unroll
    for (int i = 0; i < 4; i++) g_proto[tid * 4 + i] = p[i] * sc;
}

// sim_fwd[xy] = fd_tgt[xy,:] . proto  (one warp per xy)
__global__ void simfwd_kernel(float* __restrict__ out) {
    int w = threadIdx.x >> 5, l = threadIdx.x & 31;
    int xy = blockIdx.x * 8 + w;
    const float* row = g_xnt + (size_t)2 * NPIX * CDIM + (size_t)xy * CDIM;
    float acc = 0.f;
    for (int c = l; c < CDIM; c += 32) acc += row[c] * g_proto[c];
#pragma unroll
    for (int o = 16; o; o >>= 1) acc += __shfl_xor_sync(0xFFFFFFFFu, acc, o);
    if (l == 0) out[xy] = acc;
}

// argmax over hw for each (s, xy)
__global__ void argmax_part_kernel(const float* __restrict__ sim) {
    int s = blockIdx.z;
    int xy = blockIdx.x * 256 + threadIdx.x;
    int hw0 = blockIdx.y * 256;
    const float* base = sim + (size_t)s * NPIX * NPIX + xy;
    float best = -1e30f;
    int bi = hw0;
#pragma unroll 4
    for (int i = 0; i < 256; i++) {
        float v = base[(size_t)(hw0 + i) * NPIX];
        if (v > best) { best = v; bi = hw0 + i; }
    }
    unsigned int key = __float_as_uint(best);
    key = (key & 0x80000000u) ? ~key : (key | 0x80000000u);
    unsigned long long pk = ((unsigned long long)key << 32) | (unsigned int)(0xFFFFFFFFu - (unsigned)bi);
    atomicMax(&g_part[s * NPIX + xy], pk);
}

__global__ void votes_kernel(float* __restrict__ out) {
    int xy = blockIdx.x * blockDim.x + threadIdx.x;
    int v = 0;
#pragma unroll
    for (int s = 0; s < SREF; s++) {
        unsigned long long pk = g_part[s * NPIX + xy];
        int hw = (int)(0xFFFFFFFFu - (unsigned int)(pk & 0xFFFFFFFFu));
        v += g_mask[s * NPIX + hw];
    }
    out[xy] = (float)v;
}

// ---------------- launch ----------------
extern "C" void kernel_launch(void* const* d_in, const int* in_sizes, int n_in,
                              void* d_out, int out_size) {
    const float* fmaps = (const float*)d_in[0];
    const void*  masks = d_in[1];
    const float* basis = (const float*)d_in[2];
    float* out = (float*)d_out;

    float* sim    = out;
    float* simfwd = out + (size_t)SREF * NPIX * NPIX;
    float* votes  = simfwd + NPIX;

    float *xnt, *xhi, *xlo, *chi, *clo, *bT_hi, *bT_lo, *bc_hi, *bc_lo;
    cudaGetSymbolAddress((void**)&xnt,   g_xnt);
    cudaGetSymbolAddress((void**)&xhi,   g_hi);
    cudaGetSymbolAddress((void**)&xlo,   g_lo);
    cudaGetSymbolAddress((void**)&chi,   g_chi);
    cudaGetSymbolAddress((void**)&clo,   g_clo);
    cudaGetSymbolAddress((void**)&bT_hi, g_bT_hi);
    cudaGetSymbolAddress((void**)&bT_lo, g_bT_lo);
    cudaGetSymbolAddress((void**)&bc_hi, g_bc_hi);
    cudaGetSymbolAddress((void**)&bc_lo, g_bc_lo);

    cudaFuncSetAttribute(tc_gemm<0>, cudaFuncAttributeMaxDynamicSharedMemorySize, SMEM_DYN);
    cudaFuncSetAttribute(tc_gemm<1>, cudaFuncAttributeMaxDynamicSharedMemorySize, SMEM_DYN);
    cudaFuncSetAttribute(tc_gemm<2>, cudaFuncAttributeMaxDynamicSharedMemorySize, SMEM_DYN);

    // 1. norms + transpose/scale/split -> xnt, xhi, xlo  [t][n][c]
    norms_kernel<<<dim3(NPIX / 32, TN_), dim3(32, 8)>>>(fmaps);
    transpose_scale_split_kernel<<<dim3(CDIM / 32, NPIX / 32, TN_), dim3(32, 8)>>>(fmaps);

    // 2. basis operand prep (both orientations, zero-padded to 512)
    basis_prepT_kernel<<<dim3(CDIM / 32, KPAD / 32), dim3(32, 8)>>>(basis);
    basis_prepC_kernel<<<CDIM * KPAD / 256, 256>>>(basis);

    // 3. coef[t][n][j] = Xn . basisT^T  (M=4096, N=512, K=1024), split output
    tc_gemm<1><<<dim3(KPAD / BN, NPIX / BM, TN_), 256, SMEM_DYN>>>(
        xhi, xlo, CDIM, (size_t)NPIX * CDIM,
        bT_hi, bT_lo, CDIM, 0,
        chi, clo, KPAD, (size_t)NPIX * KPAD,
        nullptr, 0, CDIM);

    // 4. xnt <- xnt - coef . basis^T  IN PLACE  (M=4096, N=1024, K=512)
    tc_gemm<2><<<dim3(CDIM / BN, NPIX / BM, TN_), 256, SMEM_DYN>>>(
        chi, clo, KPAD, (size_t)NPIX * KPAD,
        bc_hi, bc_lo, KPAD, 0,
        xnt, nullptr, CDIM, (size_t)NPIX * CDIM,
        xnt, (size_t)NPIX * CDIM, KPAD);

    // 5. row-normalize in place -> fd (fp32 + refreshed hi/lo split)
    norm_rows_split_kernel<<<TN_ * NPIX, 256>>>();

    // 6. mask prep + prototypes
    mask_prep_kernel<<<1, 256>>>(masks);
    protos_part_kernel<<<dim3(CDIM / 256, 32, SREF), 256>>>();
    protos_reduce_kernel<<<dim3(CDIM / 256, SREF), 256>>>();
    proto_kernel<<<1, 256>>>();

    // 7. sim_fwd
    simfwd_kernel<<<NPIX / 8, 256>>>(simfwd);

    // 8. sim[s] = fd_ref[s] . fd_tgt^T  (M=4096, N=4096, K=1024)
    tc_gemm<0><<<dim3(NPIX / BN, NPIX / BM, SREF), 256, SMEM_DYN>>>(
        xhi, xlo, CDIM, (size_t)NPIX * CDIM,
        xhi + (size_t)2 * NPIX * CDIM, xlo + (size_t)2 * NPIX * CDIM, CDIM, 0,
        sim, nullptr, NPIX, (size_t)NPIX * NPIX,
        nullptr, 0, CDIM);

    // 9. argmax + votes
    argmax_part_kernel<<<dim3(16, 16, SREF), 256>>>(sim);
    votes_kernel<<<NPIX / 256, 256>>>(votes);
}

// round 9
// speedup vs baseline: 1.7248x; 1.1339x over previous
#include <cuda_runtime.h>
#include <cuda_bf16.h>
#include <math.h>
#include <stdint.h>

// Problem constants
#define CDIM 1024
#define NPIX 4096      // 64*64
#define TN_  3         // S_REF + 1
#define KSVD 500
#define KPAD 512
#define SREF 2

// GEMM tile config
#define BM 128
#define BN 128
#define BK 32
#define PA 36                      // fp32 tile pitch (words): 144B rows, conflict-free
#define PB16 20                    // bf16-pair tile pitch (words): 80B rows, conflict-free
#define OFF_AHB 4608
#define OFF_ALB 7168
#define OFF_BHI 9728
#define OFF_BHB 14336
#define OFF_BLB 16896
#define STAGE_WORDS 19456
#define SMEM_DYN (2 * STAGE_WORDS * 4)   // 155648 B

// ---------------- scratch (device globals; no allocation) ----------------
__device__ float          g_xnt[(size_t)TN_ * NPIX * CDIM];  // fp32 [t][n][c]; Xn->Xd->fd
__device__ float          g_hi [(size_t)TN_ * NPIX * CDIM];  // tf32 hi (fp32 words)
__device__ __nv_bfloat16  g_hb [(size_t)TN_ * NPIX * CDIM];  // bf16(hi)
__device__ __nv_bfloat16  g_lb [(size_t)TN_ * NPIX * CDIM];  // bf16(lo)
__device__ float          g_chi[(size_t)TN_ * NPIX * KPAD];  // coef hi [t][n][j]
__device__ __nv_bfloat16  g_chb[(size_t)TN_ * NPIX * KPAD];
__device__ __nv_bfloat16  g_clb[(size_t)TN_ * NPIX * KPAD];
__device__ float          g_bT_hi[KPAD * CDIM];              // basisT [j][c]
__device__ __nv_bfloat16  g_bT_hb[KPAD * CDIM];
__device__ __nv_bfloat16  g_bT_lb[KPAD * CDIM];
__device__ float          g_bc_hi[CDIM * KPAD];              // basis [c][j]
__device__ __nv_bfloat16  g_bc_hb[CDIM * KPAD];
__device__ __nv_bfloat16  g_bc_lb[CDIM * KPAD];
__device__ float g_nrm[TN_ * NPIX];
__device__ float g_protpart[SREF * 32 * CDIM];
__device__ float g_protos[SREF * CDIM];
__device__ float g_counts[SREF];
__device__ float g_proto[CDIM];
__device__ int   g_mask[SREF * NPIX];
__device__ unsigned long long g_part[SREF * NPIX];

// ---------------- helpers ----------------
__device__ __forceinline__ uint32_t smem_u32(const void* p) {
    uint32_t a;
    asm("{ .reg .u64 t; cvta.to.shared.u64 t, %1; cvt.u32.u64 %0, t; }" : "=r"(a) : "l"(p));
    return a;
}
__device__ __forceinline__ void cp16(uint32_t dst, const void* src) {
    asm volatile("cp.async.cg.shared.global [%0], [%1], 16;" :: "r"(dst), "l"(src) : "memory");
}
#define CP_COMMIT() asm volatile("cp.async.commit_group;" ::: "memory")
#define CP_WAIT1()  asm volatile("cp.async.wait_group 1;" ::: "memory")
#define CP_WAIT0()  asm volatile("cp.async.wait_group 0;" ::: "memory")

__device__ __forceinline__ uint32_t f2tf32(float x) {
    uint32_t r;
    asm("cvt.rna.tf32.f32 %0, %1;" : "=r"(r) : "f"(x));
    return r;
}
__device__ __forceinline__ void mma_tf32(float* c, const uint32_t* a, const uint32_t* b) {
    asm volatile(
        "mma.sync.aligned.m16n8k8.row.col.f32.tf32.tf32.f32 "
        "{%0,%1,%2,%3},{%4,%5,%6,%7},{%8,%9},{%0,%1,%2,%3};\n"
        : "+f"(c[0]), "+f"(c[1]), "+f"(c[2]), "+f"(c[3])
        : "r"(a[0]), "r"(a[1]), "r"(a[2]), "r"(a[3]), "r"(b[0]), "r"(b[1]));
}
__device__ __forceinline__ void mma_bf16(float* c, const uint32_t* a, const uint32_t* b) {
    asm volatile(
        "mma.sync.aligned.m16n8k16.row.col.f32.bf16.bf16.f32 "
        "{%0,%1,%2,%3},{%4,%5,%6,%7},{%8,%9},{%0,%1,%2,%3};\n"
        : "+f"(c[0]), "+f"(c[1]), "+f"(c[2]), "+f"(c[3])
        : "r"(a[0]), "r"(a[1]), "r"(a[2]), "r"(a[3]), "r"(b[0]), "r"(b[1]));
}

// ================= mixed tf32/bf16 split GEMM: D[m][n] = sum_k A[m,k]*B[n,k] =================
// hi.hi in tf32; hi.lo + lo.hi in bf16 (k16). K mult of 32, M,N mult of 128.
// MODE 0: O1 = D. MODE 1: O1=hi(D) fp32 + Ohb/Olb bf16 split. MODE 2: O1 = Csub - D (in-place ok).
template <int MODE>
__global__ void __launch_bounds__(256, 1)
tc_gemm(const float* __restrict__ Ahi, const __nv_bfloat16* __restrict__ Ahb,
        const __nv_bfloat16* __restrict__ Alb, int lda, size_t zsA,
        const float* __restrict__ Bhi, const __nv_bfloat16* __restrict__ Bhb,
        const __nv_bfloat16* __restrict__ Blb, int ldb, size_t zsB,
        float* __restrict__ O1, __nv_bfloat16* __restrict__ Ohb, __nv_bfloat16* __restrict__ Olb,
        int ldo, size_t zsO, const float* __restrict__ Csub, size_t zsC, int K) {
    extern __shared__ uint32_t sm[];
    const int tid = threadIdx.x;
    const int lane = tid & 31, w = tid >> 5;
    const int wm = w & 1, wn = w >> 1;        // 2 x 4 warps, warp tile 64x32
    const int g = lane >> 2, tg = lane & 3;

    Ahi += (size_t)blockIdx.z * zsA;  Ahb += (size_t)blockIdx.z * zsA;  Alb += (size_t)blockIdx.z * zsA;
    Bhi += (size_t)blockIdx.z * zsB;  Bhb += (size_t)blockIdx.z * zsB;  Blb += (size_t)blockIdx.z * zsB;
    O1  += (size_t)blockIdx.z * zsO;
    if (MODE == 1) { Ohb += (size_t)blockIdx.z * zsO; Olb += (size_t)blockIdx.z * zsO; }
    if (MODE == 2) Csub += (size_t)blockIdx.z * zsC;
    const int m0 = blockIdx.y * BM;
    const int n0 = blockIdx.x * BN;

    const uint32_t sbase = smem_u32(sm);

    float acc[4][4][4];
#pragma unroll
    for (int i = 0; i < 4; i++)
#pragma unroll
        for (int j = 0; j < 4; j++)
#pragma unroll
            for (int r = 0; r < 4; r++) acc[i][j][r] = 0.f;

    auto issue = [&](int st, int k0) {
        uint32_t sb = sbase + (uint32_t)st * STAGE_WORDS * 4;
        // fp32 hi tiles: 1024 chunks each
#pragma unroll
        for (int p = 0; p < 4; p++) {
            int ch = p * 256 + tid;
            int row = ch >> 3, q = ch & 7;
            cp16(sb + (uint32_t)(row * PA + q * 4) * 4, Ahi + (size_t)(m0 + row) * lda + k0 + q * 4);
            cp16(sb + (uint32_t)(OFF_BHI + row * PA + q * 4) * 4, Bhi + (size_t)(n0 + row) * ldb + k0 + q * 4);
        }
        // bf16 tiles: 512 chunks each
#pragma unroll
        for (int p = 0; p < 2; p++) {
            int ch = p * 256 + tid;
            int row = ch >> 2, q = ch & 3;
            uint32_t d = (uint32_t)(row * PB16 + q * 4) * 4;
            cp16(sb + (OFF_AHB * 4) + d, (const char*)Ahb + ((size_t)(m0 + row) * lda + k0) * 2 + q * 16);
            cp16(sb + (OFF_ALB * 4) + d, (const char*)Alb + ((size_t)(m0 + row) * lda + k0) * 2 + q * 16);
            cp16(sb + (OFF_BHB * 4) + d, (const char*)Bhb + ((size_t)(n0 + row) * ldb + k0) * 2 + q * 16);
            cp16(sb + (OFF_BLB * 4) + d, (const char*)Blb + ((size_t)(n0 + row) * ldb + k0) * 2 + q * 16);
        }
    };

    issue(0, 0);
    CP_COMMIT();

    const int NT = K >> 5;
    for (int it = 0; it < NT; it++) {
        if (it + 1 < NT) {
            issue((it + 1) & 1, (it + 1) * BK);
            CP_COMMIT();
            CP_WAIT1();
        } else {
            CP_WAIT0();
        }
        __syncthreads();

        const uint32_t* stg = sm + (size_t)(it & 1) * STAGE_WORDS;
        const uint32_t* sAhi = stg;
        const uint32_t* sAhb = stg + OFF_AHB;
        const uint32_t* sAlb = stg + OFF_ALB;
        const uint32_t* sBhi = stg + OFF_BHI;
        const uint32_t* sBhb = stg + OFF_BHB;
        const uint32_t* sBlb = stg + OFF_BLB;

#pragma unroll
        for (int kh = 0; kh < BK; kh += 16) {
            // ---- hi.hi (tf32, two k8 slices) ----
#pragma unroll
            for (int s = 0; s < 2; s++) {
                const int ks = kh + s * 8;
                uint32_t ah[4][4], bh[4][2];
#pragma unroll
                for (int i = 0; i < 4; i++) {
                    int m = wm * 64 + i * 16 + g;
                    ah[i][0] = sAhi[m * PA + ks + tg];
                    ah[i][1] = sAhi[(m + 8) * PA + ks + tg];
                    ah[i][2] = sAhi[m * PA + ks + tg + 4];
                    ah[i][3] = sAhi[(m + 8) * PA + ks + tg + 4];
                }
#pragma unroll
                for (int j = 0; j < 4; j++) {
                    int n = wn * 32 + j * 8 + g;
                    bh[j][0] = sBhi[n * PA + ks + tg];
                    bh[j][1] = sBhi[n * PA + ks + tg + 4];
                }
#pragma unroll
                for (int i = 0; i < 4; i++)
#pragma unroll
                    for (int j = 0; j < 4; j++) mma_tf32(acc[i][j], ah[i], bh[j]);
            }
            // ---- cross terms (bf16 k16) ----
            const int kw = kh >> 1;
            {
                uint32_t ax[4][4], bx[4][2];
#pragma unroll
                for (int i = 0; i < 4; i++) {
                    int m = wm * 64 + i * 16 + g;
                    ax[i][0] = sAhb[m * PB16 + kw + tg];
                    ax[i][1] = sAhb[(m + 8) * PB16 + kw + tg];
                    ax[i][2] = sAhb[m * PB16 + kw + tg + 4];
                    ax[i][3] = sAhb[(m + 8) * PB16 + kw + tg + 4];
                }
#pragma unroll
                for (int j = 0; j < 4; j++) {
                    int n = wn * 32 + j * 8 + g;
                    bx[j][0] = sBlb[n * PB16 + kw + tg];
                    bx[j][1] = sBlb[n * PB16 + kw + tg + 4];
                }
#pragma unroll
                for (int i = 0; i < 4; i++)
#pragma unroll
                    for (int j = 0; j < 4; j++) mma_bf16(acc[i][j], ax[i], bx[j]);
            }
            {
                uint32_t ax[4][4], bx[4][2];
#pragma unroll
                for (int i = 0; i < 4; i++) {
                    int m = wm * 64 + i * 16 + g;
                    ax[i][0] = sAlb[m * PB16 + kw + tg];
                    ax[i][1] = sAlb[(m + 8) * PB16 + kw + tg];
                    ax[i][2] = sAlb[m * PB16 + kw + tg + 4];
                    ax[i][3] = sAlb[(m + 8) * PB16 + kw + tg + 4];
                }
#pragma unroll
                for (int j = 0; j < 4; j++) {
                    int n = wn * 32 + j * 8 + g;
                    bx[j][0] = sBhb[n * PB16 + kw + tg];
                    bx[j][1] = sBhb[n * PB16 + kw + tg + 4];
                }
#pragma unroll
                for (int i = 0; i < 4; i++)
#pragma unroll
                    for (int j = 0; j < 4; j++) mma_bf16(acc[i][j], ax[i], bx[j]);
            }
        }
        __syncthreads();
    }

    // ---- epilogue ----
#pragma unroll
    for (int i = 0; i < 4; i++) {
        int r0 = m0 + wm * 64 + i * 16 + g;
        int r1 = r0 + 8;
#pragma unroll
        for (int j = 0; j < 4; j++) {
            int cc = n0 + wn * 32 + j * 8 + 2 * tg;
            float v0 = acc[i][j][0], v1 = acc[i][j][1];
            float v2 = acc[i][j][2], v3 = acc[i][j][3];
            size_t o0 = (size_t)r0 * ldo + cc;
            size_t o1 = (size_t)r1 * ldo + cc;
            if (MODE == 0) {
                O1[o0] = v0; O1[o0 + 1] = v1;
                O1[o1] = v2; O1[o1 + 1] = v3;
            } else if (MODE == 1) {
                float h0 = __uint_as_float(f2tf32(v0)), h1 = __uint_as_float(f2tf32(v1));
                float h2 = __uint_as_float(f2tf32(v2)), h3 = __uint_as_float(f2tf32(v3));
                O1[o0] = h0; O1[o0 + 1] = h1;
                O1[o1] = h2; O1[o1 + 1] = h3;
                *(__nv_bfloat162*)(Ohb + o0) = __nv_bfloat162(__float2bfloat16_rn(h0), __float2bfloat16_rn(h1));
                *(__nv_bfloat162*)(Ohb + o1) = __nv_bfloat162(__float2bfloat16_rn(h2), __float2bfloat16_rn(h3));
                *(__nv_bfloat162*)(Olb + o0) = __nv_bfloat162(__float2bfloat16_rn(v0 - h0), __float2bfloat16_rn(v1 - h1));
                *(__nv_bfloat162*)(Olb + o1) = __nv_bfloat162(__float2bfloat16_rn(v2 - h2), __float2bfloat16_rn(v3 - h3));
            } else {
                O1[o0]     = Csub[o0]     - v0;
                O1[o0 + 1] = Csub[o0 + 1] - v1;
                O1[o1]     = Csub[o1]     - v2;
                O1[o1 + 1] = Csub[o1 + 1] - v3;
            }
        }
    }
}

// ================= prep / aux kernels =================

__device__ __forceinline__ void split3(float v, float* hi, __nv_bfloat16* hb, __nv_bfloat16* lb) {
    float h = __uint_as_float(f2tf32(v));
    *hi = h;
    *hb = __float2bfloat16_rn(h);
    *lb = __float2bfloat16_rn(v - h);
}

// channel norms of fmaps[t][c][n]
__global__ void norms_kernel(const float* __restrict__ in) {
    int t = blockIdx.y;
    int pix = blockIdx.x * 32 + threadIdx.x;
    int part = threadIdx.y;
    const float* p = in + (size_t)t * CDIM * NPIX + pix;
    float ss = 0.f;
#pragma unroll 8
    for (int c = part * 128; c < part * 128 + 128; c++) {
        float v = p[(size_t)c * NPIX];
        ss += v * v;
    }
    __shared__ float sh[8][33];
    sh[part][threadIdx.x] = ss;
    __syncthreads();
    if (part == 0) {
        float tot = 0.f;
#pragma unroll
        for (int r = 0; r < 8; r++) tot += sh[r][threadIdx.x];
        g_nrm[t * NPIX + pix] = 1.0f / fmaxf(sqrtf(tot), 1e-12f);
    }
}

// XnT[t][n][c] = fmaps[t][c][n] * nrm[t][n], write fp32 + 3-way split
__global__ void transpose_scale_split_kernel(const float* __restrict__ in) {
    __shared__ float sh[32][33];
    int t = blockIdx.z;
    int c0 = blockIdx.x * 32, n0 = blockIdx.y * 32;
    const float* p = in + (size_t)t * CDIM * NPIX;
    for (int i = threadIdx.y; i < 32; i += 8)
        sh[i][threadIdx.x] = p[(size_t)(c0 + i) * NPIX + n0 + threadIdx.x];
    __syncthreads();
    size_t base = (size_t)t * NPIX * CDIM;
    for (int i = threadIdx.y; i < 32; i += 8) {
        int n = n0 + i;
        float v = sh[threadIdx.x][i] * g_nrm[t * NPIX + n];
        size_t o = base + (size_t)n * CDIM + c0 + threadIdx.x;
        g_xnt[o] = v;
        split3(v, &g_hi[o], &g_hb[o], &g_lb[o]);
    }
}

// basisT[j][c] split (rows j>=500 zero)
__global__ void basis_prepT_kernel(const float* __restrict__ basis) {
    __shared__ float sh[32][33];
    int c0 = blockIdx.x * 32, j0 = blockIdx.y * 32;
    for (int i = threadIdx.y; i < 32; i += 8) {
        int j = j0 + threadIdx.x;
        sh[i][threadIdx.x] = (j < KSVD) ? basis[(size_t)(c0 + i) * KSVD + j] : 0.f;
    }
    __syncthreads();
    for (int i = threadIdx.y; i < 32; i += 8) {
        size_t o = (size_t)(j0 + i) * CDIM + c0 + threadIdx.x;
        split3(sh[threadIdx.x][i], &g_bT_hi[o], &g_bT_hb[o], &g_bT_lb[o]);
    }
}

// basis[c][j] split (cols j>=500 zero)
__global__ void basis_prepC_kernel(const float* __restrict__ basis) {
    int idx = blockIdx.x * 256 + threadIdx.x;
    int c = idx >> 9, j = idx & (KPAD - 1);
    float v = (j < KSVD) ? basis[(size_t)c * KSVD + j] : 0.f;
    split3(v, &g_bc_hi[idx], &g_bc_hb[idx], &g_bc_lb[idx]);
}

// row L2 normalize in place + refresh splits
__global__ void norm_rows_split_kernel() {
    size_t row = blockIdx.x;
    float4* p = (float4*)(g_xnt + row * CDIM);
    int tid = threadIdx.x;
    float4 v = p[tid];
    float ss = v.x * v.x + v.y * v.y + v.z * v.z + v.w * v.w;
    __shared__ float sh[256];
    sh[tid] = ss;
    __syncthreads();
    for (int s = 128; s > 0; s >>= 1) {
        if (tid < s) sh[tid] += sh[tid + s];
        __syncthreads();
    }
    float sc = 1.0f / fmaxf(sqrtf(sh[0]), 1e-12f);
    v.x *= sc; v.y *= sc; v.z *= sc; v.w *= sc;
    p[tid] = v;
    size_t o = row * CDIM + tid * 4;
    float vv[4] = {v.x, v.y, v.z, v.w};
#pragma unroll
    for (int r = 0; r < 4; r++) split3(vv[r], &g_hi[o + r], &g_hb[o + r], &g_lb[o + r]);
}

// mask prep: dtype-sniff, counts, partmax init
__global__ void mask_prep_kernel(const void* __restrict__ mraw) {
    __shared__ int flag;
    __shared__ float sh0[256], sh1[256];
    int tid = threadIdx.x;
    if (tid == 0) flag = 0;
    __syncthreads();
    const unsigned char* b = (const unsigned char*)mraw;
    int local = 0;
    for (int i = tid; i < SREF * NPIX; i += blockDim.x)
        if ((i & 3) != 0 && b[i] != 0) local = 1;
    if (local) atomicOr(&flag, 1);
    __syncthreads();
    int isbyte = flag;
    float c0 = 0.f, c1 = 0.f;
    for (int i = tid; i < SREF * NPIX; i += blockDim.x) {
        int v = isbyte ? (int)b[i] : ((const int*)mraw)[i];
        int m = (v != 0) ? 1 : 0;
        g_mask[i] = m;
        if (i < NPIX) c0 += (float)m; else c1 += (float)m;
        g_part[i] = 0ull;
    }
    sh0[tid] = c0; sh1[tid] = c1;
    __syncthreads();
    for (int s = 128; s > 0; s >>= 1) {
        if (tid < s) { sh0[tid] += sh0[tid + s]; sh1[tid] += sh1[tid + s]; }
        __syncthreads();
    }
    if (tid == 0) { g_counts[0] = sh0[0]; g_counts[1] = sh1[0]; }
}

// protos partials (deterministic)
__global__ void protos_part_kernel() {
    int s = blockIdx.z, nb = blockIdx.y;
    int c = blockIdx.x * 256 + threadIdx.x;
    const float* base = g_xnt + (size_t)s * NPIX * CDIM;
    float acc = 0.f;
    for (int n = nb * 128; n < nb * 128 + 128; n++)
        if (g_mask[s * NPIX + n]) acc += base[(size_t)n * CDIM + c];
    g_protpart[(s * 32 + nb) * CDIM + c] = acc;
}
__global__ void protos_reduce_kernel() {
    int s = blockIdx.y;
    int c = blockIdx.x * 256 + threadIdx.x;
    float a = 0.f;
#pragma unroll
    for (int nb = 0; nb < 32; nb++) a += g_protpart[(s * 32 + nb) * CDIM + c];
    g_protos[s * CDIM + c] = a;
}

__global__ void proto_kernel() {
    __shared__ float sh[256];
    int tid = threadIdx.x;
    float c0 = fmaxf(g_counts[0], 1.f);
    float c1 = fmaxf(g_counts[1], 1.f);
    float p[4];
    float ss = 0.f;
#pragma unroll
    for (int i = 0; i < 4; i++) {
        int c = tid * 4 + i;
        p[i] = 0.5f * (g_protos[c] / c0 + g_protos[CDIM + c] / c1);
        ss += p[i] * p[i];
    }
    sh[tid] = ss;
    __syncthreads();
    for (int st = 128; st > 0; st >>= 1) {
        if (tid < st) sh[tid] += sh[tid + st];
        __syncthreads();
    }
    float sc = 1.0f / fmaxf(sqrtf(sh[0]), 1e-12f);
#pragma unroll
    for (int i = 0; i < 4; i++) g_proto[tid * 4 + i] = p[i] * sc;
}

// sim_fwd[xy] = fd_tgt[xy,:] . proto  (one warp per xy)
__global__ void simfwd_kernel(float* __restrict__ out) {
    int w = threadIdx.x >> 5, l = threadIdx.x & 31;
    int xy = blockIdx.x * 8 + w;
    const float* row = g_xnt + (size_t)2 * NPIX * CDIM + (size_t)xy * CDIM;
    float acc = 0.f;
    for (int c = l; c < CDIM; c += 32) acc += row[c] * g_proto[c];
#pragma unroll
    for (int o = 16; o; o >>= 1) acc += __shfl_xor_sync(0xFFFFFFFFu, acc, o);
    if (l == 0) out[xy] = acc;
}

// argmax over hw for each (s, xy)
__global__ void argmax_part_kernel(const float* __restrict__ sim) {
    int s = blockIdx.z;
    int xy = blockIdx.x * 256 + threadIdx.x;
    int hw0 = blockIdx.y * 256;
    const float* base = sim + (size_t)s * NPIX * NPIX + xy;
    float best = -1e30f;
    int bi = hw0;
#pragma unroll 4
    for (int i = 0; i < 256; i++) {
        float v = base[(size_t)(hw0 + i) * NPIX];
        if (v > best) { best = v; bi = hw0 + i; }
    }
    unsigned int key = __float_as_uint(best);
    key = (key & 0x80000000u) ? ~key : (key | 0x80000000u);
    unsigned long long pk = ((unsigned long long)key << 32) | (unsigned int)(0xFFFFFFFFu - (unsigned)bi);
    atomicMax(&g_part[s * NPIX + xy], pk);
}

__global__ void votes_kernel(float* __restrict__ out) {
    int xy = blockIdx.x * blockDim.x + threadIdx.x;
    int v = 0;
#pragma unroll
    for (int s = 0; s < SREF; s++) {
        unsigned long long pk = g_part[s * NPIX + xy];
        int hw = (int)(0xFFFFFFFFu - (unsigned int)(pk & 0xFFFFFFFFu));
        v += g_mask[s * NPIX + hw];
    }
    out[xy] = (float)v;
}

// ---------------- launch ----------------
extern "C" void kernel_launch(void* const* d_in, const int* in_sizes, int n_in,
                              void* d_out, int out_size) {
    const float* fmaps = (const float*)d_in[0];
    const void*  masks = d_in[1];
    const float* basis = (const float*)d_in[2];
    float* out = (float*)d_out;

    float* sim    = out;
    float* simfwd = out + (size_t)SREF * NPIX * NPIX;
    float* votes  = simfwd + NPIX;

    float *xhi, *chi, *bT_hi, *bc_hi;
    __nv_bfloat16 *xhb, *xlb, *chb, *clb, *bT_hb, *bT_lb, *bc_hb, *bc_lb;
    cudaGetSymbolAddress((void**)&xhi,   g_hi);
    cudaGetSymbolAddress((void**)&xhb,   g_hb);
    cudaGetSymbolAddress((void**)&xlb,   g_lb);
    cudaGetSymbolAddress((void**)&chi,   g_chi);
    cudaGetSymbolAddress((void**)&chb,   g_chb);
    cudaGetSymbolAddress((void**)&clb,   g_clb);
    cudaGetSymbolAddress((void**)&bT_hi, g_bT_hi);
    cudaGetSymbolAddress((void**)&bT_hb, g_bT_hb);
    cudaGetSymbolAddress((void**)&bT_lb, g_bT_lb);
    cudaGetSymbolAddress((void**)&bc_hi, g_bc_hi);
    cudaGetSymbolAddress((void**)&bc_hb, g_bc_hb);
    cudaGetSymbolAddress((void**)&bc_lb, g_bc_lb);
    float* xnt;
    cudaGetSymbolAddress((void**)&xnt, g_xnt);

    cudaFuncSetAttribute(tc_gemm<0>, cudaFuncAttributeMaxDynamicSharedMemorySize, SMEM_DYN);
    cudaFuncSetAttribute(tc_gemm<1>, cudaFuncAttributeMaxDynamicSharedMemorySize, SMEM_DYN);
    cudaFuncSetAttribute(tc_gemm<2>, cudaFuncAttributeMaxDynamicSharedMemorySize, SMEM_DYN);

    // 1. norms + transpose/scale/split
    norms_kernel<<<dim3(NPIX / 32, TN_), dim3(32, 8)>>>(fmaps);
    transpose_scale_split_kernel<<<dim3(CDIM / 32, NPIX / 32, TN_), dim3(32, 8)>>>(fmaps);

    // 2. basis operand prep (both orientations, zero-padded to 512)
    basis_prepT_kernel<<<dim3(CDIM / 32, KPAD / 32), dim3(32, 8)>>>(basis);
    basis_prepC_kernel<<<CDIM * KPAD / 256, 256>>>(basis);

    // 3. coef[t][n][j] = Xn . basisT^T  (M=4096, N=512, K=1024), split output
    tc_gemm<1><<<dim3(KPAD / BN, NPIX / BM, TN_), 256, SMEM_DYN>>>(
        xhi, xhb, xlb, CDIM, (size_t)NPIX * CDIM,
        bT_hi, bT_hb, bT_lb, CDIM, 0,
        chi, chb, clb, KPAD, (size_t)NPIX * KPAD,
        nullptr, 0, CDIM);

    // 4. xnt <- xnt - coef . basis^T  IN PLACE  (M=4096, N=1024, K=512)
    tc_gemm<2><<<dim3(CDIM / BN, NPIX / BM, TN_), 256, SMEM_DYN>>>(
        chi, chb, clb, KPAD, (size_t)NPIX * KPAD,
        bc_hi, bc_hb, bc_lb, KPAD, 0,
        xnt, nullptr, nullptr, CDIM, (size_t)NPIX * CDIM,
        xnt, (size_t)NPIX * CDIM, KPAD);

    // 5. row-normalize in place -> fd + refreshed splits
    norm_rows_split_kernel<<<TN_ * NPIX, 256>>>();

    // 6. mask prep + prototypes
    mask_prep_kernel<<<1, 256>>>(masks);
    protos_part_kernel<<<dim3(CDIM / 256, 32, SREF), 256>>>();
    protos_reduce_kernel<<<dim3(CDIM / 256, SREF), 256>>>();
    proto_kernel<<<1, 256>>>();

    // 7. sim_fwd
    simfwd_kernel<<<NPIX / 8, 256>>>(simfwd);

    // 8. sim[s] = fd_ref[s] . fd_tgt^T  (M=4096, N=4096, K=1024)
    tc_gemm<0><<<dim3(NPIX / BN, NPIX / BM, SREF), 256, SMEM_DYN>>>(
        xhi, xhb, xlb, CDIM, (size_t)NPIX * CDIM,
        xhi + (size_t)2 * NPIX * CDIM, xhb + (size_t)2 * NPIX * CDIM, xlb + (size_t)2 * NPIX * CDIM, CDIM, 0,
        sim, nullptr, nullptr, NPIX, (size_t)NPIX * NPIX,
        nullptr, 0, CDIM);

    // 9. argmax + votes
    argmax_part_kernel<<<dim3(16, 16, SREF), 256>>>(sim);
    votes_kernel<<<NPIX / 256, 256>>>(votes);
}

// round 11
// speedup vs baseline: 2.4661x; 1.4298x over previous
#include <cuda_runtime.h>
#include <cuda_bf16.h>
#include <math.h>
#include <stdint.h>

// Problem constants
#define CDIM 1024
#define NPIX 4096      // 64*64
#define TN_  3         // S_REF + 1
#define KSVD 500
#define KPAD 512
#define SREF 2

// GEMM tile config: BM=BN=128, BK=32, 256 threads (8 warps 2x4), warp tile 64x32
#define BK 32
#define PROW 80                      // smem row pitch bytes (64B data + 16B pad) -> LDSM conflict-free
#define OFF_AH 0
#define OFF_AL 10240
#define OFF_BH 20480
#define OFF_BL 30720
#define STAGE_B 40960
#define SMEM_DYN (2 * STAGE_B)       // 81920 B

// ---------------- scratch (device globals; no allocation) ----------------
__device__ float          g_xnt[(size_t)TN_ * NPIX * CDIM];  // fp32 [t][n][c]; Xn->Xd->fd
__device__ __nv_bfloat16  g_h  [(size_t)TN_ * NPIX * CDIM];  // bf16 hi
__device__ __nv_bfloat16  g_l  [(size_t)TN_ * NPIX * CDIM];  // bf16 lo (v - hi)
__device__ __nv_bfloat16  g_ch [(size_t)TN_ * NPIX * KPAD];  // coef hi [t][n][j]
__device__ __nv_bfloat16  g_cl [(size_t)TN_ * NPIX * KPAD];
__device__ __nv_bfloat16  g_bT_h[KPAD * CDIM];               // basisT [j][c]
__device__ __nv_bfloat16  g_bT_l[KPAD * CDIM];
__device__ __nv_bfloat16  g_bc_h[CDIM * KPAD];               // basis [c][j]
__device__ __nv_bfloat16  g_bc_l[CDIM * KPAD];
__device__ float g_nrm[TN_ * NPIX];
__device__ float g_protpart[SREF * 32 * CDIM];
__device__ float g_protos[SREF * CDIM];
__device__ float g_counts[SREF];
__device__ float g_proto[CDIM];
__device__ int   g_mask[SREF * NPIX];
__device__ unsigned long long g_part[SREF * NPIX];

// ---------------- helpers ----------------
__device__ __forceinline__ uint32_t smem_u32(const void* p) {
    uint32_t a;
    asm("{ .reg .u64 t; cvta.to.shared.u64 t, %1; cvt.u32.u64 %0, t; }" : "=r"(a) : "l"(p));
    return a;
}
__device__ __forceinline__ void cp16(uint32_t dst, const void* src) {
    asm volatile("cp.async.cg.shared.global [%0], [%1], 16;" :: "r"(dst), "l"(src) : "memory");
}
#define CP_COMMIT() asm volatile("cp.async.commit_group;" ::: "memory")
#define CP_WAIT1()  asm volatile("cp.async.wait_group 1;" ::: "memory")
#define CP_WAIT0()  asm volatile("cp.async.wait_group 0;" ::: "memory")

__device__ __forceinline__ void ldsm4(uint32_t& r0, uint32_t& r1, uint32_t& r2, uint32_t& r3,
                                      uint32_t addr) {
    asm volatile("ldmatrix.sync.aligned.m8n8.x4.shared.b16 {%0,%1,%2,%3},[%4];"
                 : "=r"(r0), "=r"(r1), "=r"(r2), "=r"(r3) : "r"(addr));
}
__device__ __forceinline__ void mma_bf16(float* c, const uint32_t* a, const uint32_t* b) {
    asm volatile(
        "mma.sync.aligned.m16n8k16.row.col.f32.bf16.bf16.f32 "
        "{%0,%1,%2,%3},{%4,%5,%6,%7},{%8,%9},{%0,%1,%2,%3};\n"
        : "+f"(c[0]), "+f"(c[1]), "+f"(c[2]), "+f"(c[3])
        : "r"(a[0]), "r"(a[1]), "r"(a[2]), "r"(a[3]), "r"(b[0]), "r"(b[1]));
}
__device__ __forceinline__ void split2(float v, __nv_bfloat16* h, __nv_bfloat16* l) {
    __nv_bfloat16 hb = __float2bfloat16_rn(v);
    *h = hb;
    *l = __float2bfloat16_rn(v - __bfloat162float(hb));
}

// ================= bf16 2-split GEMM: D[m][n] = sum_k A[m,k]*B[n,k] =================
// A = Ah+Al, B = Bh+Bl (bf16 pairs). D = Ah.Bh + Ah.Bl + Al.Bh (l.l dropped, ~2^-18 rel).
// K mult of 32, M,N mult of 128.
// MODE 0: O1 = D (fp32). MODE 1: Oh/Ol = bf16 2-split of D. MODE 2: O1 = Csub - D (in-place ok).
template <int MODE>
__global__ void __launch_bounds__(256, 1)
tc_gemm(const __nv_bfloat16* __restrict__ Ah, const __nv_bfloat16* __restrict__ Al, int lda, size_t zsA,
        const __nv_bfloat16* __restrict__ Bh, const __nv_bfloat16* __restrict__ Bl, int ldb, size_t zsB,
        float* __restrict__ O1, __nv_bfloat16* __restrict__ Oh, __nv_bfloat16* __restrict__ Ol,
        int ldo, size_t zsO, const float* __restrict__ Csub, size_t zsC, int K) {
    extern __shared__ char sm[];
    const int tid = threadIdx.x;
    const int lane = tid & 31, w = tid >> 5;
    const int wm = w & 1, wn = w >> 1;        // warp tile 64x32
    const int g = lane >> 2, tg = lane & 3;

    Ah += (size_t)blockIdx.z * zsA;  Al += (size_t)blockIdx.z * zsA;
    Bh += (size_t)blockIdx.z * zsB;  Bl += (size_t)blockIdx.z * zsB;
    if (MODE != 1) O1 += (size_t)blockIdx.z * zsO;
    if (MODE == 1) { Oh += (size_t)blockIdx.z * zsO; Ol += (size_t)blockIdx.z * zsO; }
    if (MODE == 2) Csub += (size_t)blockIdx.z * zsC;
    const int m0 = blockIdx.y * 128;
    const int n0 = blockIdx.x * 128;

    const uint32_t sbase = smem_u32(sm);

    // ldmatrix per-lane address offsets (within a tile, stage-relative)
    uint32_t aoff[4], boff[2];
#pragma unroll
    for (int i = 0; i < 4; i++)
        aoff[i] = (uint32_t)((wm * 64 + i * 16 + (lane & 15)) * PROW + (lane >> 4) * 16);
    {
        int sel = lane >> 3;
#pragma unroll
        for (int p = 0; p < 2; p++) {
            int n = wn * 32 + p * 16 + ((sel >> 1) * 8) + (lane & 7);
            boff[p] = (uint32_t)(n * PROW + (sel & 1) * 16);
        }
    }

    float acc[4][4][4];
#pragma unroll
    for (int i = 0; i < 4; i++)
#pragma unroll
        for (int j = 0; j < 4; j++)
#pragma unroll
            for (int r = 0; r < 4; r++) acc[i][j][r] = 0.f;

    auto issue = [&](int st, int k0) {
        uint32_t sb = sbase + (uint32_t)st * STAGE_B;
#pragma unroll
        for (int p = 0; p < 2; p++) {
            int ch = p * 256 + tid;          // 0..511
            int row = ch >> 2, q = ch & 3;
            uint32_t off = (uint32_t)(row * PROW + q * 16);
            const char* ga = (const char*)Ah + ((size_t)(m0 + row) * lda + k0) * 2 + q * 16;
            const char* gl = (const char*)Al + ((size_t)(m0 + row) * lda + k0) * 2 + q * 16;
            const char* gb = (const char*)Bh + ((size_t)(n0 + row) * ldb + k0) * 2 + q * 16;
            const char* gc = (const char*)Bl + ((size_t)(n0 + row) * ldb + k0) * 2 + q * 16;
            cp16(sb + OFF_AH + off, ga);
            cp16(sb + OFF_AL + off, gl);
            cp16(sb + OFF_BH + off, gb);
            cp16(sb + OFF_BL + off, gc);
        }
    };

    issue(0, 0);
    CP_COMMIT();

    const int NT = K >> 5;
    for (int it = 0; it < NT; it++) {
        if (it + 1 < NT) {
            issue((it + 1) & 1, (it + 1) * BK);
            CP_COMMIT();
            CP_WAIT1();
        } else {
            CP_WAIT0();
        }
        __syncthreads();

        const uint32_t s0 = sbase + (uint32_t)(it & 1) * STAGE_B;
#pragma unroll
        for (int khb = 0; khb < 64; khb += 32) {   // two k16 halves (byte offset)
            uint32_t ah[4][4], al[4][4], bh[4][2], bl[4][2];
#pragma unroll
            for (int i = 0; i < 4; i++) {
                ldsm4(ah[i][0], ah[i][1], ah[i][2], ah[i][3], s0 + OFF_AH + aoff[i] + khb);
                ldsm4(al[i][0], al[i][1], al[i][2], al[i][3], s0 + OFF_AL + aoff[i] + khb);
            }
#pragma unroll
            for (int p = 0; p < 2; p++) {
                ldsm4(bh[2 * p][0], bh[2 * p][1], bh[2 * p + 1][0], bh[2 * p + 1][1],
                      s0 + OFF_BH + boff[p] + khb);
                ldsm4(bl[2 * p][0], bl[2 * p][1], bl[2 * p + 1][0], bl[2 * p + 1][1],
                      s0 + OFF_BL + boff[p] + khb);
            }
            // term 1: h.h
#pragma unroll
            for (int i = 0; i < 4; i++)
#pragma unroll
                for (int j = 0; j < 4; j++) mma_bf16(acc[i][j], ah[i], bh[j]);
            // term 2: h.l
#pragma unroll
            for (int i = 0; i < 4; i++)
#pragma unroll
                for (int j = 0; j < 4; j++) mma_bf16(acc[i][j], ah[i], bl[j]);
            // term 3: l.h
#pragma unroll
            for (int i = 0; i < 4; i++)
#pragma unroll
                for (int j = 0; j < 4; j++) mma_bf16(acc[i][j], al[i], bh[j]);
        }
        __syncthreads();
    }

    // ---- epilogue ----
#pragma unroll
    for (int i = 0; i < 4; i++) {
        int r0 = m0 + wm * 64 + i * 16 + g;
        int r1 = r0 + 8;
#pragma unroll
        for (int j = 0; j < 4; j++) {
            int cc = n0 + wn * 32 + j * 8 + 2 * tg;
            float v0 = acc[i][j][0], v1 = acc[i][j][1];
            float v2 = acc[i][j][2], v3 = acc[i][j][3];
            size_t o0 = (size_t)r0 * ldo + cc;
            size_t o1 = (size_t)r1 * ldo + cc;
            if (MODE == 0) {
                O1[o0] = v0; O1[o0 + 1] = v1;
                O1[o1] = v2; O1[o1 + 1] = v3;
            } else if (MODE == 1) {
                __nv_bfloat16 h0, l0, h1, l1, h2, l2, h3, l3;
                split2(v0, &h0, &l0); split2(v1, &h1, &l1);
                split2(v2, &h2, &l2); split2(v3, &h3, &l3);
                *(__nv_bfloat162*)(Oh + o0) = __nv_bfloat162(h0, h1);
                *(__nv_bfloat162*)(Oh + o1) = __nv_bfloat162(h2, h3);
                *(__nv_bfloat162*)(Ol + o0) = __nv_bfloat162(l0, l1);
                *(__nv_bfloat162*)(Ol + o1) = __nv_bfloat162(l2, l3);
            } else {
                O1[o0]     = Csub[o0]     - v0;
                O1[o0 + 1] = Csub[o0 + 1] - v1;
                O1[o1]     = Csub[o1]     - v2;
                O1[o1 + 1] = Csub[o1 + 1] - v3;
            }
        }
    }
}

// ================= prep / aux kernels =================

// channel norms of fmaps[t][c][n]
__global__ void norms_kernel(const float* __restrict__ in) {
    int t = blockIdx.y;
    int pix = blockIdx.x * 32 + threadIdx.x;
    int part = threadIdx.y;
    const float* p = in + (size_t)t * CDIM * NPIX + pix;
    float ss = 0.f;
#pragma unroll 8
    for (int c = part * 128; c < part * 128 + 128; c++) {
        float v = p[(size_t)c * NPIX];
        ss += v * v;
    }
    __shared__ float sh[8][33];
    sh[part][threadIdx.x] = ss;
    __syncthreads();
    if (part == 0) {
        float tot = 0.f;
#pragma unroll
        for (int r = 0; r < 8; r++) tot += sh[r][threadIdx.x];
        g_nrm[t * NPIX + pix] = 1.0f / fmaxf(sqrtf(tot), 1e-12f);
    }
}

// XnT[t][n][c] = fmaps[t][c][n] * nrm[t][n], write fp32 + bf16 h/l
__global__ void transpose_scale_split_kernel(const float* __restrict__ in) {
    __shared__ float sh[32][33];
    int t = blockIdx.z;
    int c0 = blockIdx.x * 32, n0 = blockIdx.y * 32;
    const float* p = in + (size_t)t * CDIM * NPIX;
    for (int i = threadIdx.y; i < 32; i += 8)
        sh[i][threadIdx.x] = p[(size_t)(c0 + i) * NPIX + n0 + threadIdx.x];
    __syncthreads();
    size_t base = (size_t)t * NPIX * CDIM;
    for (int i = threadIdx.y; i < 32; i += 8) {
        int n = n0 + i;
        float v = sh[threadIdx.x][i] * g_nrm[t * NPIX + n];
        size_t o = base + (size_t)n * CDIM + c0 + threadIdx.x;
        g_xnt[o] = v;
        split2(v, &g_h[o], &g_l[o]);
    }
}

// basisT[j][c] split (rows j>=500 zero)
__global__ void basis_prepT_kernel(const float* __restrict__ basis) {
    __shared__ float sh[32][33];
    int c0 = blockIdx.x * 32, j0 = blockIdx.y * 32;
    for (int i = threadIdx.y; i < 32; i += 8) {
        int j = j0 + threadIdx.x;
        sh[i][threadIdx.x] = (j < KSVD) ? basis[(size_t)(c0 + i) * KSVD + j] : 0.f;
    }
    __syncthreads();
    for (int i = threadIdx.y; i < 32; i += 8) {
        size_t o = (size_t)(j0 + i) * CDIM + c0 + threadIdx.x;
        split2(sh[threadIdx.x][i], &g_bT_h[o], &g_bT_l[o]);
    }
}

// basis[c][j] split (cols j>=500 zero)
__global__ void basis_prepC_kernel(const float* __restrict__ basis) {
    int idx = blockIdx.x * 256 + threadIdx.x;
    int c = idx >> 9, j = idx & (KPAD - 1);
    float v = (j < KSVD) ? basis[(size_t)c * KSVD + j] : 0.f;
    split2(v, &g_bc_h[idx], &g_bc_l[idx]);
}

// row L2 normalize in place + refresh bf16 splits
__global__ void norm_rows_split_kernel() {
    size_t row = blockIdx.x;
    float4* p = (float4*)(g_xnt + row * CDIM);
    int tid = threadIdx.x;
    float4 v = p[tid];
    float ss = v.x * v.x + v.y * v.y + v.z * v.z + v.w * v.w;
    __shared__ float sh[256];
    sh[tid] = ss;
    __syncthreads();
    for (int s = 128; s > 0; s >>= 1) {
        if (tid < s) sh[tid] += sh[tid + s];
        __syncthreads();
    }
    float sc = 1.0f / fmaxf(sqrtf(sh[0]), 1e-12f);
    v.x *= sc; v.y *= sc; v.z *= sc; v.w *= sc;
    p[tid] = v;
    size_t o = row * CDIM + tid * 4;
    float vv[4] = {v.x, v.y, v.z, v.w};
#pragma unroll
    for (int r = 0; r < 4; r++) split2(vv[r], &g_h[o + r], &g_l[o + r]);
}

// mask prep: dtype-sniff, counts, partmax init
__global__ void mask_prep_kernel(const void* __restrict__ mraw) {
    __shared__ int flag;
    __shared__ float sh0[256], sh1[256];
    int tid = threadIdx.x;
    if (tid == 0) flag = 0;
    __syncthreads();
    const unsigned char* b = (const unsigned char*)mraw;
    int local = 0;
    for (int i = tid; i < SREF * NPIX; i += blockDim.x)
        if ((i & 3) != 0 && b[i] != 0) local = 1;
    if (local) atomicOr(&flag, 1);
    __syncthreads();
    int isbyte = flag;
    float c0 = 0.f, c1 = 0.f;
    for (int i = tid; i < SREF * NPIX; i += blockDim.x) {
        int v = isbyte ? (int)b[i] : ((const int*)mraw)[i];
        int m = (v != 0) ? 1 : 0;
        g_mask[i] = m;
        if (i < NPIX) c0 += (float)m; else c1 += (float)m;
        g_part[i] = 0ull;
    }
    sh0[tid] = c0; sh1[tid] = c1;
    __syncthreads();
    for (int s = 128; s > 0; s >>= 1) {
        if (tid < s) { sh0[tid] += sh0[tid + s]; sh1[tid] += sh1[tid + s]; }
        __syncthreads();
    }
    if (tid == 0) { g_counts[0] = sh0[0]; g_counts[1] = sh1[0]; }
}

// protos partials (deterministic)
__global__ void protos_part_kernel() {
    int s = blockIdx.z, nb = blockIdx.y;
    int c = blockIdx.x * 256 + threadIdx.x;
    const float* base = g_xnt + (size_t)s * NPIX * CDIM;
    float acc = 0.f;
    for (int n = nb * 128; n < nb * 128 + 128; n++)
        if (g_mask[s * NPIX + n]) acc += base[(size_t)n * CDIM + c];
    g_protpart[(s * 32 + nb) * CDIM + c] = acc;
}
__global__ void protos_reduce_kernel() {
    int s = blockIdx.y;
    int c = blockIdx.x * 256 + threadIdx.x;
    float a = 0.f;
#pragma unroll
    for (int nb = 0; nb < 32; nb++) a += g_protpart[(s * 32 + nb) * CDIM + c];
    g_protos[s * CDIM + c] = a;
}

__global__ void proto_kernel() {
    __shared__ float sh[256];
    int tid = threadIdx.x;
    float c0 = fmaxf(g_counts[0], 1.f);
    float c1 = fmaxf(g_counts[1], 1.f);
    float p[4];
    float ss = 0.f;
#pragma unroll
    for (int i = 0; i < 4; i++) {
        int c = tid * 4 + i;
        p[i] = 0.5f * (g_protos[c] / c0 + g_protos[CDIM + c] / c1);
        ss += p[i] * p[i];
    }
    sh[tid] = ss;
    __syncthreads();
    for (int st = 128; st > 0; st >>= 1) {
        if (tid < st) sh[tid] += sh[tid + st];
        __syncthreads();
    }
    float sc = 1.0f / fmaxf(sqrtf(sh[0]), 1e-12f);
#pragma unroll
    for (int i = 0; i < 4; i++) g_proto[tid * 4 + i] = p[i] * sc;
}

// sim_fwd[xy] = fd_tgt[xy,:] . proto  (one warp per xy)
__global__ void simfwd_kernel(float* __restrict__ out) {
    int w = threadIdx.x >> 5, l = threadIdx.x & 31;
    int xy = blockIdx.x * 8 + w;
    const float* row = g_xnt + (size_t)2 * NPIX * CDIM + (size_t)xy * CDIM;
    float acc = 0.f;
    for (int c = l; c < CDIM; c += 32) acc += row[c] * g_proto[c];
#pragma unroll
    for (int o = 16; o; o >>= 1) acc += __shfl_xor_sync(0xFFFFFFFFu, acc, o);
    if (l == 0) out[xy] = acc;
}

// argmax over hw for each (s, xy)
__global__ void argmax_part_kernel(const float* __restrict__ sim) {
    int s = blockIdx.z;
    int xy = blockIdx.x * 256 + threadIdx.x;
    int hw0 = blockIdx.y * 256;
    const float* base = sim + (size_t)s * NPIX * NPIX + xy;
    float best = -1e30f;
    int bi = hw0;
#pragma unroll 4
    for (int i = 0; i < 256; i++) {
        float v = base[(size_t)(hw0 + i) * NPIX];
        if (v > best) { best = v; bi = hw0 + i; }
    }
    unsigned int key = __float_as_uint(best);
    key = (key & 0x80000000u) ? ~key : (key | 0x80000000u);
    unsigned long long pk = ((unsigned long long)key << 32) | (unsigned int)(0xFFFFFFFFu - (unsigned)bi);
    atomicMax(&g_part[s * NPIX + xy], pk);
}

__global__ void votes_kernel(float* __restrict__ out) {
    int xy = blockIdx.x * blockDim.x + threadIdx.x;
    int v = 0;
#pragma unroll
    for (int s = 0; s < SREF; s++) {
        unsigned long long pk = g_part[s * NPIX + xy];
        int hw = (int)(0xFFFFFFFFu - (unsigned int)(pk & 0xFFFFFFFFu));
        v += g_mask[s * NPIX + hw];
    }
    out[xy] = (float)v;
}

// ---------------- launch ----------------
extern "C" void kernel_launch(void* const* d_in, const int* in_sizes, int n_in,
                              void* d_out, int out_size) {
    const float* fmaps = (const float*)d_in[0];
    const void*  masks = d_in[1];
    const float* basis = (const float*)d_in[2];
    float* out = (float*)d_out;

    float* sim    = out;
    float* simfwd = out + (size_t)SREF * NPIX * NPIX;
    float* votes  = simfwd + NPIX;

    float* xnt;
    __nv_bfloat16 *xh, *xl, *ch, *cl, *bT_h, *bT_l, *bc_h, *bc_l;
    cudaGetSymbolAddress((void**)&xnt,  g_xnt);
    cudaGetSymbolAddress((void**)&xh,   g_h);
    cudaGetSymbolAddress((void**)&xl,   g_l);
    cudaGetSymbolAddress((void**)&ch,   g_ch);
    cudaGetSymbolAddress((void**)&cl,   g_cl);
    cudaGetSymbolAddress((void**)&bT_h, g_bT_h);
    cudaGetSymbolAddress((void**)&bT_l, g_bT_l);
    cudaGetSymbolAddress((void**)&bc_h, g_bc_h);
    cudaGetSymbolAddress((void**)&bc_l, g_bc_l);

    cudaFuncSetAttribute(tc_gemm<0>, cudaFuncAttributeMaxDynamicSharedMemorySize, SMEM_DYN);
    cudaFuncSetAttribute(tc_gemm<1>, cudaFuncAttributeMaxDynamicSharedMemorySize, SMEM_DYN);
    cudaFuncSetAttribute(tc_gemm<2>, cudaFuncAttributeMaxDynamicSharedMemorySize, SMEM_DYN);

    // 1. norms + transpose/scale/split
    norms_kernel<<<dim3(NPIX / 32, TN_), dim3(32, 8)>>>(fmaps);
    transpose_scale_split_kernel<<<dim3(CDIM / 32, NPIX / 32, TN_), dim3(32, 8)>>>(fmaps);

    // 2. basis operand prep (both orientations, zero-padded to 512)
    basis_prepT_kernel<<<dim3(CDIM / 32, KPAD / 32), dim3(32, 8)>>>(basis);
    basis_prepC_kernel<<<CDIM * KPAD / 256, 256>>>(basis);

    // 3. coef[t][n][j] = Xn . basisT^T  (M=4096, N=512, K=1024), bf16-split output
    tc_gemm<1><<<dim3(KPAD / 128, NPIX / 128, TN_), 256, SMEM_DYN>>>(
        xh, xl, CDIM, (size_t)NPIX * CDIM,
        bT_h, bT_l, CDIM, 0,
        nullptr, ch, cl, KPAD, (size_t)NPIX * KPAD,
        nullptr, 0, CDIM);

    // 4. xnt <- xnt - coef . basis^T  IN PLACE  (M=4096, N=1024, K=512)
    tc_gemm<2><<<dim3(CDIM / 128, NPIX / 128, TN_), 256, SMEM_DYN>>>(
        ch, cl, KPAD, (size_t)NPIX * KPAD,
        bc_h, bc_l, KPAD, 0,
        xnt, nullptr, nullptr, CDIM, (size_t)NPIX * CDIM,
        xnt, (size_t)NPIX * CDIM, KPAD);

    // 5. row-normalize in place -> fd + refreshed splits
    norm_rows_split_kernel<<<TN_ * NPIX, 256>>>();

    // 6. mask prep + prototypes
    mask_prep_kernel<<<1, 256>>>(masks);
    protos_part_kernel<<<dim3(CDIM / 256, 32, SREF), 256>>>();
    protos_reduce_kernel<<<dim3(CDIM / 256, SREF), 256>>>();
    proto_kernel<<<1, 256>>>();

    // 7. sim_fwd
    simfwd_kernel<<<NPIX / 8, 256>>>(simfwd);

    // 8. sim[s] = fd_ref[s] . fd_tgt^T  (M=4096, N=4096, K=1024)
    tc_gemm<0><<<dim3(NPIX / 128, NPIX / 128, SREF), 256, SMEM_DYN>>>(
        xh, xl, CDIM, (size_t)NPIX * CDIM,
        xh + (size_t)2 * NPIX * CDIM, xl + (size_t)2 * NPIX * CDIM, CDIM, 0,
        sim, nullptr, nullptr, NPIX, (size_t)NPIX * NPIX,
        nullptr, 0, CDIM);

    // 9. argmax + votes
    argmax_part_kernel<<<dim3(16, 16, SREF), 256>>>(sim);
    votes_kernel<<<NPIX / 256, 256>>>(votes);
}

// round 12
// speedup vs baseline: 2.4744x; 1.0034x over previous
#include <cuda_runtime.h>
#include <cuda_bf16.h>
#include <math.h>
#include <stdint.h>

// Problem constants
#define CDIM 1024
#define NPIX 4096      // 64*64
#define TN_  3         // S_REF + 1
#define KSVD 500
#define KPAD 512
#define SREF 2

// GEMM tile config: BM=BN=128, BK=32, 256 threads (8 warps 2x4), warp tile 64x32
#define BK 32
#define PROW 80                      // smem row pitch bytes (64B data + 16B pad) -> LDSM conflict-free
#define OFF_AH 0
#define OFF_AL 10240
#define OFF_BH 20480
#define OFF_BL 30720
#define STAGE_B 40960
#define SMEM_DYN (2 * STAGE_B)       // 81920 B

// ---------------- scratch (device globals; no allocation) ----------------
__device__ float          g_xnt[(size_t)TN_ * NPIX * CDIM];  // fp32 [t][n][c]; Xn->Xd->fd
__device__ __nv_bfloat16  g_h  [(size_t)TN_ * NPIX * CDIM];  // bf16 hi
__device__ __nv_bfloat16  g_l  [(size_t)TN_ * NPIX * CDIM];  // bf16 lo (v - hi)
__device__ __nv_bfloat16  g_ch [(size_t)TN_ * NPIX * KPAD];  // coef hi [t][n][j]
__device__ __nv_bfloat16  g_cl [(size_t)TN_ * NPIX * KPAD];
__device__ __nv_bfloat16  g_bT_h[KPAD * CDIM];               // basisT [j][c]
__device__ __nv_bfloat16  g_bT_l[KPAD * CDIM];
__device__ __nv_bfloat16  g_bc_h[CDIM * KPAD];               // basis [c][j]
__device__ __nv_bfloat16  g_bc_l[CDIM * KPAD];
__device__ float g_nrm[TN_ * NPIX];
__device__ float g_protpart[SREF * 32 * CDIM];
__device__ float g_protos[SREF * CDIM];
__device__ float g_counts[SREF];
__device__ float g_proto[CDIM];
__device__ int   g_mask[SREF * NPIX];
__device__ unsigned long long g_part[SREF * NPIX];

// ---------------- helpers ----------------
__device__ __forceinline__ uint32_t smem_u32(const void* p) {
    uint32_t a;
    asm("{ .reg .u64 t; cvta.to.shared.u64 t, %1; cvt.u32.u64 %0, t; }" : "=r"(a) : "l"(p));
    return a;
}
__device__ __forceinline__ void cp16(uint32_t dst, const void* src) {
    asm volatile("cp.async.cg.shared.global [%0], [%1], 16;" :: "r"(dst), "l"(src) : "memory");
}
#define CP_COMMIT() asm volatile("cp.async.commit_group;" ::: "memory")
#define CP_WAIT1()  asm volatile("cp.async.wait_group 1;" ::: "memory")
#define CP_WAIT0()  asm volatile("cp.async.wait_group 0;" ::: "memory")

__device__ __forceinline__ void ldsm4(uint32_t& r0, uint32_t& r1, uint32_t& r2, uint32_t& r3,
                                      uint32_t addr) {
    asm volatile("ldmatrix.sync.aligned.m8n8.x4.shared.b16 {%0,%1,%2,%3},[%4];"
                 : "=r"(r0), "=r"(r1), "=r"(r2), "=r"(r3) : "r"(addr));
}
__device__ __forceinline__ void mma_bf16(float* c, const uint32_t* a, const uint32_t* b) {
    asm volatile(
        "mma.sync.aligned.m16n8k16.row.col.f32.bf16.bf16.f32 "
        "{%0,%1,%2,%3},{%4,%5,%6,%7},{%8,%9},{%0,%1,%2,%3};\n"
        : "+f"(c[0]), "+f"(c[1]), "+f"(c[2]), "+f"(c[3])
        : "r"(a[0]), "r"(a[1]), "r"(a[2]), "r"(a[3]), "r"(b[0]), "r"(b[1]));
}
__device__ __forceinline__ void split2(float v, __nv_bfloat16* h, __nv_bfloat16* l) {
    __nv_bfloat16 hb = __float2bfloat16_rn(v);
    *h = hb;
    *l = __float2bfloat16_rn(v - __bfloat162float(hb));
}

// ================= bf16 2-split GEMM: D[m][n] = sum_k A[m,k]*B[n,k] =================
// A = Ah+Al, B = Bh+Bl (bf16 pairs). D = Ah.Bh + Ah.Bl + Al.Bh (l.l dropped, ~2^-18 rel).
// K mult of 32, M,N mult of 128.
// MODE 0: O1 = D (fp32). MODE 1: Oh/Ol = bf16 2-split of D. MODE 2: O1 = Csub - D (in-place ok).
template <int MODE>
__global__ void __launch_bounds__(256, 1)
tc_gemm(const __nv_bfloat16* __restrict__ Ah, const __nv_bfloat16* __restrict__ Al, int lda, size_t zsA,
        const __nv_bfloat16* __restrict__ Bh, const __nv_bfloat16* __restrict__ Bl, int ldb, size_t zsB,
        float* __restrict__ O1, __nv_bfloat16* __restrict__ Oh, __nv_bfloat16* __restrict__ Ol,
        int ldo, size_t zsO, const float* __restrict__ Csub, size_t zsC, int K) {
    extern __shared__ char sm[];
    const int tid = threadIdx.x;
    const int lane = tid & 31, w = tid >> 5;
    const int wm = w & 1, wn = w >> 1;        // warp tile 64x32
    const int g = lane >> 2, tg = lane & 3;

    Ah += (size_t)blockIdx.z * zsA;  Al += (size_t)blockIdx.z * zsA;
    Bh += (size_t)blockIdx.z * zsB;  Bl += (size_t)blockIdx.z * zsB;
    if (MODE != 1) O1 += (size_t)blockIdx.z * zsO;
    if (MODE == 1) { Oh += (size_t)blockIdx.z * zsO; Ol += (size_t)blockIdx.z * zsO; }
    if (MODE == 2) Csub += (size_t)blockIdx.z * zsC;
    const int m0 = blockIdx.y * 128;
    const int n0 = blockIdx.x * 128;

    const uint32_t sbase = smem_u32(sm);

    // ldmatrix per-lane address offsets (within a tile, stage-relative)
    uint32_t aoff[4], boff[2];
#pragma unroll
    for (int i = 0; i < 4; i++)
        aoff[i] = (uint32_t)((wm * 64 + i * 16 + (lane & 15)) * PROW + (lane >> 4) * 16);
    {
        int sel = lane >> 3;
#pragma unroll
        for (int p = 0; p < 2; p++) {
            int n = wn * 32 + p * 16 + ((sel >> 1) * 8) + (lane & 7);
            boff[p] = (uint32_t)(n * PROW + (sel & 1) * 16);
        }
    }

    float acc[4][4][4];
#pragma unroll
    for (int i = 0; i < 4; i++)
#pragma unroll
        for (int j = 0; j < 4; j++)
#pragma unroll
            for (int r = 0; r < 4; r++) acc[i][j][r] = 0.f;

    auto issue = [&](int st, int k0) {
        uint32_t sb = sbase + (uint32_t)st * STAGE_B;
#pragma unroll
        for (int p = 0; p < 2; p++) {
            int ch = p * 256 + tid;          // 0..511
            int row = ch >> 2, q = ch & 3;
            uint32_t off = (uint32_t)(row * PROW + q * 16);
            const char* ga = (const char*)Ah + ((size_t)(m0 + row) * lda + k0) * 2 + q * 16;
            const char* gl = (const char*)Al + ((size_t)(m0 + row) * lda + k0) * 2 + q * 16;
            const char* gb = (const char*)Bh + ((size_t)(n0 + row) * ldb + k0) * 2 + q * 16;
            const char* gc = (const char*)Bl + ((size_t)(n0 + row) * ldb + k0) * 2 + q * 16;
            cp16(sb + OFF_AH + off, ga);
            cp16(sb + OFF_AL + off, gl);
            cp16(sb + OFF_BH + off, gb);
            cp16(sb + OFF_BL + off, gc);
        }
    };

    issue(0, 0);
    CP_COMMIT();

    const int NT = K >> 5;
    for (int it = 0; it < NT; it++) {
        if (it + 1 < NT) {
            issue((it + 1) & 1, (it + 1) * BK);
            CP_COMMIT();
            CP_WAIT1();
        } else {
            CP_WAIT0();
        }
        __syncthreads();

        const uint32_t s0 = sbase + (uint32_t)(it & 1) * STAGE_B;
#pragma unroll
        for (int khb = 0; khb < 64; khb += 32) {   // two k16 halves (byte offset)
            uint32_t ah[4][4], al[4][4], bh[4][2], bl[4][2];
#pragma unroll
            for (int i = 0; i < 4; i++) {
                ldsm4(ah[i][0], ah[i][1], ah[i][2], ah[i][3], s0 + OFF_AH + aoff[i] + khb);
                ldsm4(al[i][0], al[i][1], al[i][2], al[i][3], s0 + OFF_AL + aoff[i] + khb);
            }
#pragma unroll
            for (int p = 0; p < 2; p++) {
                ldsm4(bh[2 * p][0], bh[2 * p][1], bh[2 * p + 1][0], bh[2 * p + 1][1],
                      s0 + OFF_BH + boff[p] + khb);
                ldsm4(bl[2 * p][0], bl[2 * p][1], bl[2 * p + 1][0], bl[2 * p + 1][1],
                      s0 + OFF_BL + boff[p] + khb);
            }
            // term 1: h.h
#pragma unroll
            for (int i = 0; i < 4; i++)
#pragma unroll
                for (int j = 0; j < 4; j++) mma_bf16(acc[i][j], ah[i], bh[j]);
            // term 2: h.l
#pragma unroll
            for (int i = 0; i < 4; i++)
#pragma unroll
                for (int j = 0; j < 4; j++) mma_bf16(acc[i][j], ah[i], bl[j]);
            // term 3: l.h
#pragma unroll
            for (int i = 0; i < 4; i++)
#pragma unroll
                for (int j = 0; j < 4; j++) mma_bf16(acc[i][j], al[i], bh[j]);
        }
        __syncthreads();
    }

    // ---- epilogue ----
#pragma unroll
    for (int i = 0; i < 4; i++) {
        int r0 = m0 + wm * 64 + i * 16 + g;
        int r1 = r0 + 8;
#pragma unroll
        for (int j = 0; j < 4; j++) {
            int cc = n0 + wn * 32 + j * 8 + 2 * tg;
            float v0 = acc[i][j][0], v1 = acc[i][j][1];
            float v2 = acc[i][j][2], v3 = acc[i][j][3];
            size_t o0 = (size_t)r0 * ldo + cc;
            size_t o1 = (size_t)r1 * ldo + cc;
            if (MODE == 0) {
                O1[o0] = v0; O1[o0 + 1] = v1;
                O1[o1] = v2; O1[o1 + 1] = v3;
            } else if (MODE == 1) {
                __nv_bfloat16 h0, l0, h1, l1, h2, l2, h3, l3;
                split2(v0, &h0, &l0); split2(v1, &h1, &l1);
                split2(v2, &h2, &l2); split2(v3, &h3, &l3);
                *(__nv_bfloat162*)(Oh + o0) = __nv_bfloat162(h0, h1);
                *(__nv_bfloat162*)(Oh + o1) = __nv_bfloat162(h2, h3);
                *(__nv_bfloat162*)(Ol + o0) = __nv_bfloat162(l0, l1);
                *(__nv_bfloat162*)(Ol + o1) = __nv_bfloat162(l2, l3);
            } else {
                O1[o0]     = Csub[o0]     - v0;
                O1[o0 + 1] = Csub[o0 + 1] - v1;
                O1[o1]     = Csub[o1]     - v2;
                O1[o1 + 1] = Csub[o1 + 1] - v3;
            }
        }
    }
}

// ================= prep / aux kernels =================

// channel norms of fmaps[t][c][n]
__global__ void norms_kernel(const float* __restrict__ in) {
    int t = blockIdx.y;
    int pix = blockIdx.x * 32 + threadIdx.x;
    int part = threadIdx.y;
    const float* p = in + (size_t)t * CDIM * NPIX + pix;
    float ss = 0.f;
#pragma unroll 8
    for (int c = part * 128; c < part * 128 + 128; c++) {
        float v = p[(size_t)c * NPIX];
        ss += v * v;
    }
    __shared__ float sh[8][33];
    sh[part][threadIdx.x] = ss;
    __syncthreads();
    if (part == 0) {
        float tot = 0.f;
#pragma unroll
        for (int r = 0; r < 8; r++) tot += sh[r][threadIdx.x];
        g_nrm[t * NPIX + pix] = 1.0f / fmaxf(sqrtf(tot), 1e-12f);
    }
}

// XnT[t][n][c] = fmaps[t][c][n] * nrm[t][n], write fp32 + bf16 h/l
__global__ void transpose_scale_split_kernel(const float* __restrict__ in) {
    __shared__ float sh[32][33];
    int t = blockIdx.z;
    int c0 = blockIdx.x * 32, n0 = blockIdx.y * 32;
    const float* p = in + (size_t)t * CDIM * NPIX;
    for (int i = threadIdx.y; i < 32; i += 8)
        sh[i][threadIdx.x] = p[(size_t)(c0 + i) * NPIX + n0 + threadIdx.x];
    __syncthreads();
    size_t base = (size_t)t * NPIX * CDIM;
    for (int i = threadIdx.y; i < 32; i += 8) {
        int n = n0 + i;
        float v = sh[threadIdx.x][i] * g_nrm[t * NPIX + n];
        size_t o = base + (size_t)n * CDIM + c0 + threadIdx.x;
        g_xnt[o] = v;
        split2(v, &g_h[o], &g_l[o]);
    }
}

// basisT[j][c] split (rows j>=500 zero)
__global__ void basis_prepT_kernel(const float* __restrict__ basis) {
    __shared__ float sh[32][33];
    int c0 = blockIdx.x * 32, j0 = blockIdx.y * 32;
    for (int i = threadIdx.y; i < 32; i += 8) {
        int j = j0 + threadIdx.x;
        sh[i][threadIdx.x] = (j < KSVD) ? basis[(size_t)(c0 + i) * KSVD + j] : 0.f;
    }
    __syncthreads();
    for (int i = threadIdx.y; i < 32; i += 8) {
        size_t o = (size_t)(j0 + i) * CDIM + c0 + threadIdx.x;
        split2(sh[threadIdx.x][i], &g_bT_h[o], &g_bT_l[o]);
    }
}

// basis[c][j] split (cols j>=500 zero)
__global__ void basis_prepC_kernel(const float* __restrict__ basis) {
    int idx = blockIdx.x * 256 + threadIdx.x;
    int c = idx >> 9, j = idx & (KPAD - 1);
    float v = (j < KSVD) ? basis[(size_t)c * KSVD + j] : 0.f;
    split2(v, &g_bc_h[idx], &g_bc_l[idx]);
}

// row L2 normalize in place + refresh bf16 splits
__global__ void norm_rows_split_kernel() {
    size_t row = blockIdx.x;
    float4* p = (float4*)(g_xnt + row * CDIM);
    int tid = threadIdx.x;
    float4 v = p[tid];
    float ss = v.x * v.x + v.y * v.y + v.z * v.z + v.w * v.w;
    __shared__ float sh[256];
    sh[tid] = ss;
    __syncthreads();
    for (int s = 128; s > 0; s >>= 1) {
        if (tid < s) sh[tid] += sh[tid + s];
        __syncthreads();
    }
    float sc = 1.0f / fmaxf(sqrtf(sh[0]), 1e-12f);
    v.x *= sc; v.y *= sc; v.z *= sc; v.w *= sc;
    p[tid] = v;
    size_t o = row * CDIM + tid * 4;
    float vv[4] = {v.x, v.y, v.z, v.w};
#pragma unroll
    for (int r = 0; r < 4; r++) split2(vv[r], &g_h[o + r], &g_l[o + r]);
}

// mask prep: dtype-sniff, counts, partmax init
__global__ void mask_prep_kernel(const void* __restrict__ mraw) {
    __shared__ int flag;
    __shared__ float sh0[256], sh1[256];
    int tid = threadIdx.x;
    if (tid == 0) flag = 0;
    __syncthreads();
    const unsigned char* b = (const unsigned char*)mraw;
    int local = 0;
    for (int i = tid; i < SREF * NPIX; i += blockDim.x)
        if ((i & 3) != 0 && b[i] != 0) local = 1;
    if (local) atomicOr(&flag, 1);
    __syncthreads();
    int isbyte = flag;
    float c0 = 0.f, c1 = 0.f;
    for (int i = tid; i < SREF * NPIX; i += blockDim.x) {
        int v = isbyte ? (int)b[i] : ((const int*)mraw)[i];
        int m = (v != 0) ? 1 : 0;
        g_mask[i] = m;
        if (i < NPIX) c0 += (float)m; else c1 += (float)m;
        g_part[i] = 0ull;
    }
    sh0[tid] = c0; sh1[tid] = c1;
    __syncthreads();
    for (int s = 128; s > 0; s >>= 1) {
        if (tid < s) { sh0[tid] += sh0[tid + s]; sh1[tid] += sh1[tid + s]; }
        __syncthreads();
    }
    if (tid == 0) { g_counts[0] = sh0[0]; g_counts[1] = sh1[0]; }
}

// protos partials (deterministic)
__global__ void protos_part_kernel() {
    int s = blockIdx.z, nb = blockIdx.y;
    int c = blockIdx.x * 256 + threadIdx.x;
    const float* base = g_xnt + (size_t)s * NPIX * CDIM;
    float acc = 0.f;
    for (int n = nb * 128; n < nb * 128 + 128; n++)
        if (g_mask[s * NPIX + n]) acc += base[(size_t)n * CDIM + c];
    g_protpart[(s * 32 + nb) * CDIM + c] = acc;
}
__global__ void protos_reduce_kernel() {
    int s = blockIdx.y;
    int c = blockIdx.x * 256 + threadIdx.x;
    float a = 0.f;
#pragma unroll
    for (int nb = 0; nb < 32; nb++) a += g_protpart[(s * 32 + nb) * CDIM + c];
    g_protos[s * CDIM + c] = a;
}

__global__ void proto_kernel() {
    __shared__ float sh[256];
    int tid = threadIdx.x;
    float c0 = fmaxf(g_counts[0], 1.f);
    float c1 = fmaxf(g_counts[1], 1.f);
    float p[4];
    float ss = 0.f;
#pragma unroll
    for (int i = 0; i < 4; i++) {
        int c = tid * 4 + i;
        p[i] = 0.5f * (g_protos[c] / c0 + g_protos[CDIM + c] / c1);
        ss += p[i] * p[i];
    }
    sh[tid] = ss;
    __syncthreads();
    for (int st = 128; st > 0; st >>= 1) {
        if (tid < st) sh[tid] += sh[tid + st];
        __syncthreads();
    }
    float sc = 1.0f / fmaxf(sqrtf(sh[0]), 1e-12f);
#pragma unroll
    for (int i = 0; i < 4; i++) g_proto[tid * 4 + i] = p[i] * sc;
}

// sim_fwd[xy] = fd_tgt[xy,:] . proto  (one warp per xy)
__global__ void simfwd_kernel(float* __restrict__ out) {
    int w = threadIdx.x >> 5, l = threadIdx.x & 31;
    int xy = blockIdx.x * 8 + w;
    const float* row = g_xnt + (size_t)2 * NPIX * CDIM + (size_t)xy * CDIM;
    float acc = 0.f;
    for (int c = l; c < CDIM; c += 32) acc += row[c] * g_proto[c];
#pragma unroll
    for (int o = 16; o; o >>= 1) acc += __shfl_xor_sync(0xFFFFFFFFu, acc, o);
    if (l == 0) out[xy] = acc;
}

// argmax over hw for each (s, xy)
__global__ void argmax_part_kernel(const float* __restrict__ sim) {
    int s = blockIdx.z;
    int xy = blockIdx.x * 256 + threadIdx.x;
    int hw0 = blockIdx.y * 256;
    const float* base = sim + (size_t)s * NPIX * NPIX + xy;
    float best = -1e30f;
    int bi = hw0;
#pragma unroll 4
    for (int i = 0; i < 256; i++) {
        float v = base[(size_t)(hw0 + i) * NPIX];
        if (v > best) { best = v; bi = hw0 + i; }
    }
    unsigned int key = __float_as_uint(best);
    key = (key & 0x80000000u) ? ~key : (key | 0x80000000u);
    unsigned long long pk = ((unsigned long long)key << 32) | (unsigned int)(0xFFFFFFFFu - (unsigned)bi);
    atomicMax(&g_part[s * NPIX + xy], pk);
}

__global__ void votes_kernel(float* __restrict__ out) {
    int xy = blockIdx.x * blockDim.x + threadIdx.x;
    int v = 0;
#pragma unroll
    for (int s = 0; s < SREF; s++) {
        unsigned long long pk = g_part[s * NPIX + xy];
        int hw = (int)(0xFFFFFFFFu - (unsigned int)(pk & 0xFFFFFFFFu));
        v += g_mask[s * NPIX + hw];
    }
    out[xy] = (float)v;
}

// ---------------- launch ----------------
extern "C" void kernel_launch(void* const* d_in, const int* in_sizes, int n_in,
                              void* d_out, int out_size) {
    const float* fmaps = (const float*)d_in[0];
    const void*  masks = d_in[1];
    const float* basis = (const float*)d_in[2];
    float* out = (float*)d_out;

    float* sim    = out;
    float* simfwd = out + (size_t)SREF * NPIX * NPIX;
    float* votes  = simfwd + NPIX;

    float* xnt;
    __nv_bfloat16 *xh, *xl, *ch, *cl, *bT_h, *bT_l, *bc_h, *bc_l;
    cudaGetSymbolAddress((void**)&xnt,  g_xnt);
    cudaGetSymbolAddress((void**)&xh,   g_h);
    cudaGetSymbolAddress((void**)&xl,   g_l);
    cudaGetSymbolAddress((void**)&ch,   g_ch);
    cudaGetSymbolAddress((void**)&cl,   g_cl);
    cudaGetSymbolAddress((void**)&bT_h, g_bT_h);
    cudaGetSymbolAddress((void**)&bT_l, g_bT_l);
    cudaGetSymbolAddress((void**)&bc_h, g_bc_h);
    cudaGetSymbolAddress((void**)&bc_l, g_bc_l);

    cudaFuncSetAttribute(tc_gemm<0>, cudaFuncAttributeMaxDynamicSharedMemorySize, SMEM_DYN);
    cudaFuncSetAttribute(tc_gemm<1>, cudaFuncAttributeMaxDynamicSharedMemorySize, SMEM_DYN);
    cudaFuncSetAttribute(tc_gemm<2>, cudaFuncAttributeMaxDynamicSharedMemorySize, SMEM_DYN);

    // 1. norms + transpose/scale/split
    norms_kernel<<<dim3(NPIX / 32, TN_), dim3(32, 8)>>>(fmaps);
    transpose_scale_split_kernel<<<dim3(CDIM / 32, NPIX / 32, TN_), dim3(32, 8)>>>(fmaps);

    // 2. basis operand prep (both orientations, zero-padded to 512)
    basis_prepT_kernel<<<dim3(CDIM / 32, KPAD / 32), dim3(32, 8)>>>(basis);
    basis_prepC_kernel<<<CDIM * KPAD / 256, 256>>>(basis);

    // 3. coef[t][n][j] = Xn . basisT^T  (M=4096, N=512, K=1024), bf16-split output
    tc_gemm<1><<<dim3(KPAD / 128, NPIX / 128, TN_), 256, SMEM_DYN>>>(
        xh, xl, CDIM, (size_t)NPIX * CDIM,
        bT_h, bT_l, CDIM, 0,
        nullptr, ch, cl, KPAD, (size_t)NPIX * KPAD,
        nullptr, 0, CDIM);

    // 4. xnt <- xnt - coef . basis^T  IN PLACE  (M=4096, N=1024, K=512)
    tc_gemm<2><<<dim3(CDIM / 128, NPIX / 128, TN_), 256, SMEM_DYN>>>(
        ch, cl, KPAD, (size_t)NPIX * KPAD,
        bc_h, bc_l, KPAD, 0,
        xnt, nullptr, nullptr, CDIM, (size_t)NPIX * CDIM,
        xnt, (size_t)NPIX * CDIM, KPAD);

    // 5. row-normalize in place -> fd + refreshed splits
    norm_rows_split_kernel<<<TN_ * NPIX, 256>>>();

    // 6. mask prep + prototypes
    mask_prep_kernel<<<1, 256>>>(masks);
    protos_part_kernel<<<dim3(CDIM / 256, 32, SREF), 256>>>();
    protos_reduce_kernel<<<dim3(CDIM / 256, SREF), 256>>>();
    proto_kernel<<<1, 256>>>();

    // 7. sim_fwd
    simfwd_kernel<<<NPIX / 8, 256>>>(simfwd);

    // 8. sim[s] = fd_ref[s] . fd_tgt^T  (M=4096, N=4096, K=1024)
    tc_gemm<0><<<dim3(NPIX / 128, NPIX / 128, SREF), 256, SMEM_DYN>>>(
        xh, xl, CDIM, (size_t)NPIX * CDIM,
        xh + (size_t)2 * NPIX * CDIM, xl + (size_t)2 * NPIX * CDIM, CDIM, 0,
        sim, nullptr, nullptr, NPIX, (size_t)NPIX * NPIX,
        nullptr, 0, CDIM);

    // 9. argmax + votes
    argmax_part_kernel<<<dim3(16, 16, SREF), 256>>>(sim);
    votes_kernel<<<NPIX / 256, 256>>>(votes);
}